// round 1
// baseline (speedup 1.0000x reference)
#include <cuda_runtime.h>
#include <cstdint>
#include <math.h>

#define TOKENS 4096
#define DMODEL 4096
#define HIDDEN 10922
#define KPAD   10944   // HIDDEN padded to a multiple of 32 (and 16B) for dp4a tiling

// ---------------- device scratch (no allocations allowed) ----------------
__device__ __align__(16) signed char g_Xi[(size_t)TOKENS * DMODEL];
__device__ __align__(16) signed char g_Gi[(size_t)HIDDEN * DMODEL];
__device__ __align__(16) signed char g_Ui[(size_t)HIDDEN * DMODEL];
__device__ __align__(16) signed char g_Di[(size_t)DMODEL * KPAD];
__device__ __align__(16) signed char g_Ai[(size_t)TOKENS * KPAD];
__device__ float g_gate[(size_t)TOKENS * HIDDEN];   // raw gate, later act
__device__ float g_up  [(size_t)TOKENS * HIDDEN];
__device__ float g_absmax[8];   // 0:x 1:wg 2:wu 3:wd 4:gate 5:up 6:act
__device__ float g_scale [8];

// ---------------- helpers ----------------
__device__ __forceinline__ void atomicMaxPosF(float* addr, float v) {
    atomicMax((unsigned int*)addr, __float_as_uint(v));
}

__device__ __forceinline__ float quant_round(float x, float s) {
    // match jnp.clip(jnp.round(t / s), -127, 127): IEEE divide + round-half-even
    float r = rintf(__fdiv_rn(x, s));
    return fminf(fmaxf(r, -127.0f), 127.0f);
}

// ---------------- init ----------------
__global__ void k_init() {
    if (threadIdx.x < 8) g_absmax[threadIdx.x] = 0.0f;
}

// ---------------- global abs-max reduce (float4) ----------------
__global__ void k_absmax(const float* __restrict__ t, size_t n4, int slot) {
    float m = 0.0f;
    size_t i  = (size_t)blockIdx.x * blockDim.x + threadIdx.x;
    size_t st = (size_t)gridDim.x * blockDim.x;
    const float4* t4 = (const float4*)t;
    for (; i < n4; i += st) {
        float4 v = t4[i];
        m = fmaxf(m, fmaxf(fmaxf(fabsf(v.x), fabsf(v.y)), fmaxf(fabsf(v.z), fabsf(v.w))));
    }
    #pragma unroll
    for (int o = 16; o; o >>= 1) m = fmaxf(m, __shfl_xor_sync(0xffffffffu, m, o));
    if ((threadIdx.x & 31) == 0) atomicMaxPosF(&g_absmax[slot], m);
}

// ---------------- scales: s = max(absmax/127, 1e-8) ----------------
__global__ void k_scales(int lo, int hi) {
    int i = threadIdx.x;
    if (i >= lo && i < hi) g_scale[i] = fmaxf(__fdiv_rn(g_absmax[i], 127.0f), 1e-8f);
}

// ---------------- quantize to int8 (vectorized, n % 4 == 0) ----------------
__global__ void k_quant(const float* __restrict__ t, signed char* __restrict__ q,
                        size_t n4, int slot) {
    float s = g_scale[slot];
    size_t i  = (size_t)blockIdx.x * blockDim.x + threadIdx.x;
    size_t st = (size_t)gridDim.x * blockDim.x;
    const float4* t4 = (const float4*)t;
    char4* q4 = (char4*)q;
    for (; i < n4; i += st) {
        float4 v = t4[i];
        char4 c;
        c.x = (signed char)(int)quant_round(v.x, s);
        c.y = (signed char)(int)quant_round(v.y, s);
        c.z = (signed char)(int)quant_round(v.z, s);
        c.w = (signed char)(int)quant_round(v.w, s);
        q4[i] = c;
    }
}

// ---------------- quantize into K-padded int8 buffer ----------------
__global__ void k_quant_pad(const float* __restrict__ t, signed char* __restrict__ q,
                            int rows, int cols, int pcols, int slot) {
    float s = g_scale[slot];
    size_t n  = (size_t)rows * pcols;
    size_t i  = (size_t)blockIdx.x * blockDim.x + threadIdx.x;
    size_t st = (size_t)gridDim.x * blockDim.x;
    for (; i < n; i += st) {
        int c = (int)(i % pcols);
        size_t r = i / pcols;
        signed char out = 0;
        if (c < cols) out = (signed char)(int)quant_round(t[r * (size_t)cols + c], s);
        q[i] = out;
    }
}

// ---------------- act = silu(q(gate)) * q(up), in place into gate; absmax ----------------
__global__ void k_act(float* __restrict__ gate, const float* __restrict__ up, size_t n4) {
    float sg = g_scale[4], su = g_scale[5];
    float m = 0.0f;
    size_t i  = (size_t)blockIdx.x * blockDim.x + threadIdx.x;
    size_t st = (size_t)gridDim.x * blockDim.x;
    float4* g4 = (float4*)gate;
    const float4* u4 = (const float4*)up;
    for (; i < n4; i += st) {
        float4 gv = g4[i];
        float4 uv = u4[i];
        float* gp = (float*)&gv;
        const float* upv = (const float*)&uv;
        #pragma unroll
        for (int k = 0; k < 4; k++) {
            float gq = quant_round(gp[k], sg) * sg;
            float uq = quant_round(upv[k], su) * su;
            float sil = gq * (1.0f / (1.0f + expf(-gq)));
            float a = sil * uq;
            gp[k] = a;
            m = fmaxf(m, fabsf(a));
        }
        g4[i] = gv;
    }
    #pragma unroll
    for (int o = 16; o; o >>= 1) m = fmaxf(m, __shfl_xor_sync(0xffffffffu, m, o));
    if ((threadIdx.x & 31) == 0) atomicMaxPosF(&g_absmax[6], m);
}

// ---------------- int8 GEMM: C[m][n] = scale * dot(A[m,:], B[n,:]) + bias[n] ----------------
// A: [M][K] int8 row-major, B: [N][K] int8 row-major, K multiple of 32 (bytes).
// 128x128 block tile, BK=32, 256 threads, 8x8 per-thread tile, dp4a.
template<bool DO_AMAX>
__global__ __launch_bounds__(256)
void k_gemm(const signed char* __restrict__ A, const signed char* __restrict__ B,
            const float* __restrict__ bias, float* __restrict__ C,
            int M, int N, int K, int sa, int sb, int amax_slot) {
    __shared__ __align__(16) int As[128][8];   // [row within tile][k4]
    __shared__ __align__(16) int Bs[8][128];   // [k4][col within tile]

    const int tid = threadIdx.x;
    const int tx = tid & 15;       // col group
    const int ty = tid >> 4;       // row group
    const int m0 = blockIdx.y * 128;
    const int n0 = blockIdx.x * 128;

    int acc[8][8];
    #pragma unroll
    for (int i = 0; i < 8; i++)
        #pragma unroll
        for (int j = 0; j < 8; j++) acc[i][j] = 0;

    const int lr = tid >> 1;         // tile row this thread loads
    const int lseg = tid & 1;        // which 16B half of the 32B K-chunk
    const size_t aoff = (size_t)(m0 + lr) * K + lseg * 16;
    const bool bvalid = (n0 + lr) < N;
    const size_t boff = bvalid ? ((size_t)(n0 + lr) * K + lseg * 16) : 0;

    const int kIters = K >> 5;
    for (int kt = 0; kt < kIters; kt++) {
        int4 a4 = *(const int4*)(A + aoff + ((size_t)kt << 5));
        int4 b4 = make_int4(0, 0, 0, 0);
        if (bvalid) b4 = *(const int4*)(B + boff + ((size_t)kt << 5));

        As[lr][lseg * 4 + 0] = a4.x;
        As[lr][lseg * 4 + 1] = a4.y;
        As[lr][lseg * 4 + 2] = a4.z;
        As[lr][lseg * 4 + 3] = a4.w;
        Bs[lseg * 4 + 0][lr] = b4.x;
        Bs[lseg * 4 + 1][lr] = b4.y;
        Bs[lseg * 4 + 2][lr] = b4.z;
        Bs[lseg * 4 + 3][lr] = b4.w;
        __syncthreads();

        #pragma unroll
        for (int g = 0; g < 2; g++) {
            int av[8][4];
            #pragma unroll
            for (int i = 0; i < 8; i++) {
                int4 v = *(const int4*)&As[ty * 8 + i][g * 4];
                av[i][0] = v.x; av[i][1] = v.y; av[i][2] = v.z; av[i][3] = v.w;
            }
            #pragma unroll
            for (int kk = 0; kk < 4; kk++) {
                int4 b0 = *(const int4*)&Bs[g * 4 + kk][tx * 8];
                int4 b1 = *(const int4*)&Bs[g * 4 + kk][tx * 8 + 4];
                #pragma unroll
                for (int i = 0; i < 8; i++) {
                    int a = av[i][kk];
                    acc[i][0] = __dp4a(a, b0.x, acc[i][0]);
                    acc[i][1] = __dp4a(a, b0.y, acc[i][1]);
                    acc[i][2] = __dp4a(a, b0.z, acc[i][2]);
                    acc[i][3] = __dp4a(a, b0.w, acc[i][3]);
                    acc[i][4] = __dp4a(a, b1.x, acc[i][4]);
                    acc[i][5] = __dp4a(a, b1.y, acc[i][5]);
                    acc[i][6] = __dp4a(a, b1.z, acc[i][6]);
                    acc[i][7] = __dp4a(a, b1.w, acc[i][7]);
                }
            }
        }
        __syncthreads();
    }

    const float sab = g_scale[sa] * g_scale[sb];
    float m = 0.0f;
    #pragma unroll
    for (int i = 0; i < 8; i++) {
        int row = m0 + ty * 8 + i;
        #pragma unroll
        for (int j = 0; j < 8; j++) {
            int col = n0 + tx * 8 + j;
            if (col < N) {
                float v = fmaf((float)acc[i][j], sab, bias[col]);
                C[(size_t)row * N + col] = v;
                if (DO_AMAX) m = fmaxf(m, fabsf(v));
            }
        }
    }
    if (DO_AMAX) {
        #pragma unroll
        for (int o = 16; o; o >>= 1) m = fmaxf(m, __shfl_xor_sync(0xffffffffu, m, o));
        if ((tid & 31) == 0) atomicMaxPosF(&g_absmax[amax_slot], m);
    }
}

// ---------------- launch ----------------
extern "C" void kernel_launch(void* const* d_in, const int* in_sizes, int n_in,
                              void* d_out, int out_size) {
    (void)in_sizes; (void)n_in; (void)out_size;
    const float* x  = (const float*)d_in[0];
    const float* wg = (const float*)d_in[1];
    const float* wu = (const float*)d_in[2];
    const float* wd = (const float*)d_in[3];
    const float* bg = (const float*)d_in[4];
    const float* bu = (const float*)d_in[5];
    const float* bd = (const float*)d_in[6];
    float* out = (float*)d_out;

    signed char *pXi, *pGi, *pUi, *pDi, *pAi;
    float *pGate, *pUp;
    cudaGetSymbolAddress((void**)&pXi, g_Xi);
    cudaGetSymbolAddress((void**)&pGi, g_Gi);
    cudaGetSymbolAddress((void**)&pUi, g_Ui);
    cudaGetSymbolAddress((void**)&pDi, g_Di);
    cudaGetSymbolAddress((void**)&pAi, g_Ai);
    cudaGetSymbolAddress((void**)&pGate, g_gate);
    cudaGetSymbolAddress((void**)&pUp, g_up);

    const int RB = 2048, RT = 256;

    k_init<<<1, 8>>>();

    // absmax of x, wg, wu, wd
    k_absmax<<<RB, RT>>>(x,  (size_t)TOKENS * DMODEL / 4, 0);
    k_absmax<<<RB, RT>>>(wg, (size_t)HIDDEN * DMODEL / 4, 1);
    k_absmax<<<RB, RT>>>(wu, (size_t)HIDDEN * DMODEL / 4, 2);
    k_absmax<<<RB, RT>>>(wd, (size_t)HIDDEN * DMODEL / 4, 3);
    k_scales<<<1, 8>>>(0, 4);

    // quantize
    k_quant<<<RB, RT>>>(x,  pXi, (size_t)TOKENS * DMODEL / 4, 0);
    k_quant<<<RB, RT>>>(wg, pGi, (size_t)HIDDEN * DMODEL / 4, 1);
    k_quant<<<RB, RT>>>(wu, pUi, (size_t)HIDDEN * DMODEL / 4, 2);
    k_quant_pad<<<RB, RT>>>(wd, pDi, DMODEL, HIDDEN, KPAD, 3);

    // gate/up GEMMs (fp32 raw outputs + absmax)
    dim3 g1((HIDDEN + 127) / 128, TOKENS / 128);
    k_gemm<true><<<g1, 256>>>(pXi, pGi, bg, pGate, TOKENS, HIDDEN, DMODEL, 0, 1, 4);
    k_gemm<true><<<g1, 256>>>(pXi, pUi, bu, pUp,   TOKENS, HIDDEN, DMODEL, 0, 2, 5);
    k_scales<<<1, 8>>>(4, 6);

    // act = silu(q(gate)) * q(up), in place into g_gate, + absmax
    k_act<<<RB, RT>>>(pGate, pUp, (size_t)TOKENS * HIDDEN / 4);
    k_scales<<<1, 8>>>(6, 7);

    // quantize act into padded int8
    k_quant_pad<<<RB, RT>>>(pGate, pAi, TOKENS, HIDDEN, KPAD, 6);

    // down GEMM -> output
    dim3 g2(DMODEL / 128, TOKENS / 128);
    k_gemm<false><<<g2, 256>>>(pAi, pDi, bd, out, TOKENS, DMODEL, KPAD, 6, 3, -1);
}

// round 3
// speedup vs baseline: 1.1496x; 1.1496x over previous
#include <cuda_runtime.h>
#include <cstdint>
#include <math.h>

#define TOKENS 4096
#define DMODEL 4096
#define HIDDEN 10922
#define HPADN  11008   // hidden padded to 128 (B rows / output cols for gate & up)
#define HPADK  10944   // hidden padded to 64  (K for down gemm)
#define NSTAGE 4

typedef signed char int8;

// ---------------- device scratch ----------------
__device__ __align__(256) int8 g_Xi[(size_t)TOKENS * DMODEL];   // A frag-packed
__device__ __align__(256) int8 g_Gi[(size_t)HPADN * DMODEL];    // B frag-packed
__device__ __align__(256) int8 g_Ui[(size_t)HPADN * DMODEL];    // B frag-packed
__device__ __align__(256) int8 g_Di[(size_t)DMODEL * HPADK];    // B frag-packed
__device__ __align__(256) int8 g_Ai[(size_t)TOKENS * HPADK];    // A frag-packed
__device__ __align__(16) float g_gate[(size_t)TOKENS * HIDDEN];
__device__ __align__(16) float g_up  [(size_t)TOKENS * HIDDEN];
__device__ float g_absmax[8];
__device__ float g_scale [8];

// ---------------- helpers ----------------
__device__ __forceinline__ void atomicMaxPosF(float* a, float v) {
    atomicMax((unsigned int*)a, __float_as_uint(v));
}
__device__ __forceinline__ float quant_round(float x, float s) {
    float r = rintf(__fdiv_rn(x, s));
    return fminf(fmaxf(r, -127.0f), 127.0f);
}
__device__ __forceinline__ uint32_t smem_u32(const void* p) {
    uint32_t a;
    asm("{ .reg .u64 t; cvta.to.shared.u64 t, %1; cvt.u32.u64 %0, t; }" : "=r"(a) : "l"(p));
    return a;
}
#define CP_ASYNC16(dst, src) \
    asm volatile("cp.async.cg.shared.global [%0], [%1], 16;" :: "r"(dst), "l"(src))
#define CP_COMMIT() asm volatile("cp.async.commit_group;")
#define CP_WAIT(n)  asm volatile("cp.async.wait_group %0;" :: "n"(n))

#define IMMA(acc, a, b) \
    asm volatile("mma.sync.aligned.m16n8k32.row.col.s32.s8.s8.s32 " \
        "{%0,%1,%2,%3}, {%4,%5,%6,%7}, {%8,%9}, {%0,%1,%2,%3};" \
        : "+r"((acc)[0]), "+r"((acc)[1]), "+r"((acc)[2]), "+r"((acc)[3]) \
        : "r"((a).x), "r"((a).y), "r"((a).z), "r"((a).w), "r"((b).x), "r"((b).y))

__global__ void k_init() { if (threadIdx.x < 8) g_absmax[threadIdx.x] = 0.0f; }

__global__ void k_absmax(const float* __restrict__ t, size_t n4, int slot) {
    float m = 0.0f;
    size_t i = (size_t)blockIdx.x * blockDim.x + threadIdx.x;
    size_t st = (size_t)gridDim.x * blockDim.x;
    const float4* t4 = (const float4*)t;
    for (; i < n4; i += st) {
        float4 v = t4[i];
        m = fmaxf(m, fmaxf(fmaxf(fabsf(v.x), fabsf(v.y)), fmaxf(fabsf(v.z), fabsf(v.w))));
    }
    #pragma unroll
    for (int o = 16; o; o >>= 1) m = fmaxf(m, __shfl_xor_sync(0xffffffffu, m, o));
    if ((threadIdx.x & 31) == 0) atomicMaxPosF(&g_absmax[slot], m);
}

__global__ void k_scales(int lo, int hi) {
    int i = threadIdx.x;
    if (i >= lo && i < hi) g_scale[i] = fmaxf(__fdiv_rn(g_absmax[i], 127.0f), 1e-8f);
}

// ---- pack A operand into m16n8k32 fragment order ----
// layout: word index w -> [mtile][k32][m16][lane][reg], 1024 words per (mtile,k32)
__global__ void k_packA(const float* __restrict__ src, int8* __restrict__ dst,
                        int mtiles, int nK32, int srcStride, int Kvalid, int slot) {
    float s = g_scale[slot];
    size_t total = (size_t)mtiles * nK32 * 1024;
    uint32_t* d32 = (uint32_t*)dst;
    int per = nK32 << 10;
    for (size_t w = (size_t)blockIdx.x * blockDim.x + threadIdx.x; w < total;
         w += (size_t)gridDim.x * blockDim.x) {
        int mtile = (int)(w / per);
        int rem = (int)(w % per);
        int k32 = rem >> 10, r2 = rem & 1023;
        int m16 = r2 >> 7, r3 = r2 & 127;
        int lane = r3 >> 2, reg = r3 & 3;
        int g = lane >> 2, t = lane & 3;
        int row = mtile * 128 + m16 * 16 + (reg & 1) * 8 + g;
        int kb = k32 * 32 + (reg >> 1) * 16 + t * 4;
        const float* p = src + (size_t)row * srcStride + kb;
        uint32_t word = 0;
        #pragma unroll
        for (int j = 0; j < 4; j++) {
            int q = 0;
            if (kb + j < Kvalid) q = (int)quant_round(__ldg(p + j), s);
            word |= ((uint32_t)(uint8_t)(int8)q) << (8 * j);
        }
        d32[w] = word;
    }
}

// ---- pack B operand (n-major rows) into fragment order ----
// word index w -> [ntile][k32][n8][lane][reg], 1024 words per (ntile,k32)
__global__ void k_packB(const float* __restrict__ src, int8* __restrict__ dst,
                        int ntiles, int nK32, int srcStride, int Nvalid, int Kvalid, int slot) {
    float s = g_scale[slot];
    size_t total = (size_t)ntiles * nK32 * 1024;
    uint32_t* d32 = (uint32_t*)dst;
    int per = nK32 << 10;
    for (size_t w = (size_t)blockIdx.x * blockDim.x + threadIdx.x; w < total;
         w += (size_t)gridDim.x * blockDim.x) {
        int ntile = (int)(w / per);
        int rem = (int)(w % per);
        int k32 = rem >> 10, r2 = rem & 1023;
        int n8 = r2 >> 6, r3 = r2 & 63;
        int lane = r3 >> 1, reg = r3 & 1;
        int g = lane >> 2, t = lane & 3;
        int n = ntile * 128 + n8 * 8 + g;
        int kb = k32 * 32 + reg * 16 + t * 4;
        uint32_t word = 0;
        if (n < Nvalid) {
            const float* p = src + (size_t)n * srcStride + kb;
            #pragma unroll
            for (int j = 0; j < 4; j++) {
                int q = 0;
                if (kb + j < Kvalid) q = (int)quant_round(__ldg(p + j), s);
                word |= ((uint32_t)(uint8_t)(int8)q) << (8 * j);
            }
        }
        d32[w] = word;
    }
}

// ---- act = silu(q(gate)) * q(up) in place into gate; absmax -> slot 6 ----
__global__ void k_act(float* __restrict__ gate, const float* __restrict__ up, size_t n4) {
    float sg = g_scale[4], su = g_scale[5];
    float m = 0.0f;
    size_t i = (size_t)blockIdx.x * blockDim.x + threadIdx.x;
    size_t st = (size_t)gridDim.x * blockDim.x;
    float4* g4 = (float4*)gate;
    const float4* u4 = (const float4*)up;
    for (; i < n4; i += st) {
        float4 gv = g4[i];
        float4 uv = u4[i];
        float* gp = (float*)&gv;
        const float* uq4 = (const float*)&uv;
        #pragma unroll
        for (int k = 0; k < 4; k++) {
            float gq = quant_round(gp[k], sg) * sg;
            float uq = quant_round(uq4[k], su) * su;
            float a = gq * (1.0f / (1.0f + expf(-gq))) * uq;
            gp[k] = a;
            m = fmaxf(m, fabsf(a));
        }
        g4[i] = gv;
    }
    #pragma unroll
    for (int o = 16; o; o >>= 1) m = fmaxf(m, __shfl_xor_sync(0xffffffffu, m, o));
    if ((threadIdx.x & 31) == 0) atomicMaxPosF(&g_absmax[6], m);
}

// ---------------- IMMA GEMM ----------------
// A frag-packed [mtile][k32][m16][lane]x16B, B frag-packed [ntile][k32][n8][lane]x8B
// C[row][col] = sab * sum + bias[col]
template<bool DO_AMAX>
__global__ void __launch_bounds__(256, 2)
k_gemm(const int8* __restrict__ A, const int8* __restrict__ B,
       const float* __restrict__ bias, float* __restrict__ C,
       int nK32, int Nvalid, int Cstride, int sa, int sb, int amax_slot) {
    extern __shared__ __align__(16) char smem[];   // NSTAGE * 16KB (A 8KB + B 8KB)
    const int tid = threadIdx.x, lane = tid & 31, wid = tid >> 5;
    const int wm = wid >> 2, wn = wid & 3;         // warp grid 2 x 4
    const int mtile = blockIdx.y, ntile = blockIdx.x;

    const char* Ag = (const char*)A + (size_t)mtile * nK32 * 4096;
    const char* Bg = (const char*)B + (size_t)ntile * nK32 * 4096;
    const int KS = nK32 >> 1;                      // 8KB (=2 k32) per stage

    int acc[4][4][4];
    #pragma unroll
    for (int i = 0; i < 4; i++)
        #pragma unroll
        for (int j = 0; j < 4; j++)
            #pragma unroll
            for (int r = 0; r < 4; r++) acc[i][j][r] = 0;

    const uint32_t sbase = smem_u32(smem);

    // per-thread copy offsets: 256 threads x 16B = 4KB; A needs 2 waves, B 2 waves
    auto issue = [&](int s) {
        uint32_t buf = sbase + (uint32_t)(s % NSTAGE) * 16384u;
        const char* ga = Ag + (size_t)s * 8192;
        const char* gb = Bg + (size_t)s * 8192;
        uint32_t o = (uint32_t)tid * 16u;
        CP_ASYNC16(buf + o,          ga + o);
        CP_ASYNC16(buf + o + 4096,   ga + o + 4096);
        CP_ASYNC16(buf + o + 8192,   gb + o);
        CP_ASYNC16(buf + o + 12288,  gb + o + 4096);
    };

    int s = 0;
    #pragma unroll
    for (int p = 0; p < NSTAGE - 1; p++) {
        if (s < KS) { issue(s); s++; }
        CP_COMMIT();
    }

    for (int c = 0; c < KS; c++) {
        CP_WAIT(NSTAGE - 2);
        __syncthreads();
        const char* bufA = smem + (c % NSTAGE) * 16384;
        const char* bufB = bufA + 8192;
        #pragma unroll
        for (int kk = 0; kk < 2; kk++) {
            int4 av[4];
            int2 bv[4];
            #pragma unroll
            for (int i = 0; i < 4; i++)
                av[i] = *(const int4*)(bufA + (((kk * 8 + wm * 4 + i) * 32 + lane) << 4));
            #pragma unroll
            for (int j = 0; j < 4; j++)
                bv[j] = *(const int2*)(bufB + (((kk * 16 + wn * 4 + j) * 32 + lane) << 3));
            #pragma unroll
            for (int i = 0; i < 4; i++)
                #pragma unroll
                for (int j = 0; j < 4; j++)
                    IMMA(acc[i][j], av[i], bv[j]);
        }
        __syncthreads();
        if (s < KS) { issue(s); s++; }
        CP_COMMIT();
    }

    // epilogue
    const float sab = g_scale[sa] * g_scale[sb];
    const int g = lane >> 2, t = lane & 3;
    float vmax = 0.0f;
    #pragma unroll
    for (int i = 0; i < 4; i++) {
        int row0 = mtile * 128 + wm * 64 + i * 16 + g;
        #pragma unroll
        for (int j = 0; j < 4; j++) {
            int col = ntile * 128 + wn * 32 + j * 8 + t * 2;
            if (col < Nvalid) {
                float b0 = __ldg(&bias[col]), b1 = __ldg(&bias[col + 1]);
                float2 v0, v1;
                v0.x = fmaf((float)acc[i][j][0], sab, b0);
                v0.y = fmaf((float)acc[i][j][1], sab, b1);
                v1.x = fmaf((float)acc[i][j][2], sab, b0);
                v1.y = fmaf((float)acc[i][j][3], sab, b1);
                *(float2*)(C + (size_t)row0 * Cstride + col) = v0;
                *(float2*)(C + (size_t)(row0 + 8) * Cstride + col) = v1;
                if (DO_AMAX) {
                    vmax = fmaxf(vmax, fmaxf(fmaxf(fabsf(v0.x), fabsf(v0.y)),
                                             fmaxf(fabsf(v1.x), fabsf(v1.y))));
                }
            }
        }
    }
    if (DO_AMAX) {
        #pragma unroll
        for (int o = 16; o; o >>= 1) vmax = fmaxf(vmax, __shfl_xor_sync(0xffffffffu, vmax, o));
        if (lane == 0) atomicMaxPosF(&g_absmax[amax_slot], vmax);
    }
}

// ---------------- launch ----------------
extern "C" void kernel_launch(void* const* d_in, const int* in_sizes, int n_in,
                              void* d_out, int out_size) {
    (void)in_sizes; (void)n_in; (void)out_size;
    const float* x  = (const float*)d_in[0];
    const float* wg = (const float*)d_in[1];
    const float* wu = (const float*)d_in[2];
    const float* wd = (const float*)d_in[3];
    const float* bg = (const float*)d_in[4];
    const float* bu = (const float*)d_in[5];
    const float* bd = (const float*)d_in[6];
    float* out = (float*)d_out;

    int8 *pXi, *pGi, *pUi, *pDi, *pAi;
    float *pGate, *pUp;
    cudaGetSymbolAddress((void**)&pXi, g_Xi);
    cudaGetSymbolAddress((void**)&pGi, g_Gi);
    cudaGetSymbolAddress((void**)&pUi, g_Ui);
    cudaGetSymbolAddress((void**)&pDi, g_Di);
    cudaGetSymbolAddress((void**)&pAi, g_Ai);
    cudaGetSymbolAddress((void**)&pGate, g_gate);
    cudaGetSymbolAddress((void**)&pUp, g_up);

    cudaFuncSetAttribute(k_gemm<true>,  cudaFuncAttributeMaxDynamicSharedMemorySize, NSTAGE * 16384);
    cudaFuncSetAttribute(k_gemm<false>, cudaFuncAttributeMaxDynamicSharedMemorySize, NSTAGE * 16384);

    const int RB = 2048, RT = 256;
    k_init<<<1, 8>>>();

    k_absmax<<<RB, RT>>>(x,  (size_t)TOKENS * DMODEL / 4, 0);
    k_absmax<<<RB, RT>>>(wg, (size_t)HIDDEN * DMODEL / 4, 1);
    k_absmax<<<RB, RT>>>(wu, (size_t)HIDDEN * DMODEL / 4, 2);
    k_absmax<<<RB, RT>>>(wd, (size_t)DMODEL * HIDDEN / 4, 3);
    k_scales<<<1, 8>>>(0, 4);

    // pack (quantize -> int8 fragment order)
    k_packA<<<RB, RT>>>(x,  pXi, TOKENS / 128, DMODEL / 32, DMODEL, DMODEL, 0);
    k_packB<<<RB, RT>>>(wg, pGi, HPADN / 128, DMODEL / 32, DMODEL, HIDDEN, DMODEL, 1);
    k_packB<<<RB, RT>>>(wu, pUi, HPADN / 128, DMODEL / 32, DMODEL, HIDDEN, DMODEL, 2);
    k_packB<<<RB, RT>>>(wd, pDi, DMODEL / 128, HPADK / 32, HIDDEN, DMODEL, HIDDEN, 3);

    // gate / up GEMMs
    dim3 g1(HPADN / 128, TOKENS / 128);
    k_gemm<true><<<g1, 256, NSTAGE * 16384>>>(pXi, pGi, bg, pGate, DMODEL / 32, HIDDEN, HIDDEN, 0, 1, 4);
    k_gemm<true><<<g1, 256, NSTAGE * 16384>>>(pXi, pUi, bu, pUp,   DMODEL / 32, HIDDEN, HIDDEN, 0, 2, 5);
    k_scales<<<1, 8>>>(4, 6);

    // activation + its scale
    k_act<<<RB, RT>>>(pGate, pUp, (size_t)TOKENS * HIDDEN / 4);
    k_scales<<<1, 8>>>(6, 7);

    // pack activations (A layout, K padded to 10944)
    k_packA<<<RB, RT>>>(pGate, pAi, TOKENS / 128, HPADK / 32, HIDDEN, HIDDEN, 6);

    // down GEMM -> out
    dim3 g2(DMODEL / 128, TOKENS / 128);
    k_gemm<false><<<g2, 256, NSTAGE * 16384>>>(pAi, pDi, bd, out, HPADK / 32, DMODEL, DMODEL, 6, 3, -1);
}

// round 5
// speedup vs baseline: 1.1652x; 1.0136x over previous
#include <cuda_runtime.h>
#include <cstdint>
#include <math.h>

#define TOKENS 4096
#define DMODEL 4096
#define HIDDEN 10922
#define HPADN  11008   // hidden padded to 128 (B rows / output cols for gate & up)
#define HPADK  10944   // hidden padded to 64; also activation buffer stride (mult of 4)
#define NSTAGE 4

typedef signed char int8;

// ---------------- device scratch ----------------
__device__ __align__(256) int8 g_Xi[(size_t)TOKENS * DMODEL];   // A frag-packed
__device__ __align__(256) int8 g_Gi[(size_t)HPADN * DMODEL];    // B frag-packed
__device__ __align__(256) int8 g_Ui[(size_t)HPADN * DMODEL];    // B frag-packed
__device__ __align__(256) int8 g_Di[(size_t)DMODEL * HPADK];    // B frag-packed
__device__ __align__(256) int8 g_Ai[(size_t)TOKENS * HPADK];    // A frag-packed
__device__ __align__(16) float g_gate[(size_t)TOKENS * HPADK];  // padded stride
__device__ __align__(16) float g_up  [(size_t)TOKENS * HPADK];  // padded stride
__device__ float g_absmax[8];   // 0:x 1:wg 2:wu 3:wd 4:gate 5:up 6:act

// ---------------- helpers ----------------
__device__ __forceinline__ void atomicMaxPosF(float* a, float v) {
    atomicMax((unsigned int*)a, __float_as_uint(v));
}
__device__ __forceinline__ float quant_round(float x, float s) {
    float r = rintf(__fdiv_rn(x, s));
    return fminf(fmaxf(r, -127.0f), 127.0f);
}
__device__ __forceinline__ float get_scale(int slot) {
    return fmaxf(__fdiv_rn(g_absmax[slot], 127.0f), 1e-8f);
}
__device__ __forceinline__ uint32_t smem_u32(const void* p) {
    uint32_t a;
    asm("{ .reg .u64 t; cvta.to.shared.u64 t, %1; cvt.u32.u64 %0, t; }" : "=r"(a) : "l"(p));
    return a;
}
__device__ __forceinline__ uint32_t pack4(float a, float b, float c, float d, float s) {
    uint32_t qa = (uint32_t)(uint8_t)(int8)(int)quant_round(a, s);
    uint32_t qb = (uint32_t)(uint8_t)(int8)(int)quant_round(b, s);
    uint32_t qc = (uint32_t)(uint8_t)(int8)(int)quant_round(c, s);
    uint32_t qd = (uint32_t)(uint8_t)(int8)(int)quant_round(d, s);
    return qa | (qb << 8) | (qc << 16) | (qd << 24);
}
// load 32 consecutive floats; p is at least 8B-aligned; a16 says 16B-aligned
__device__ __forceinline__ void load32(const float* __restrict__ p, float* f, bool a16) {
    if (a16) {
        #pragma unroll
        for (int q = 0; q < 8; q++) *(float4*)&f[q * 4] = __ldg((const float4*)p + q);
    } else {
        #pragma unroll
        for (int q = 0; q < 16; q++) *(float2*)&f[q * 2] = __ldg((const float2*)p + q);
    }
}
#define CP_ASYNC16(dst, src) \
    asm volatile("cp.async.cg.shared.global [%0], [%1], 16;" :: "r"(dst), "l"(src))
#define CP_COMMIT() asm volatile("cp.async.commit_group;")
#define CP_WAIT(n)  asm volatile("cp.async.wait_group %0;" :: "n"(n))

#define IMMA(acc, a, b) \
    asm volatile("mma.sync.aligned.m16n8k32.row.col.s32.s8.s8.s32 " \
        "{%0,%1,%2,%3}, {%4,%5,%6,%7}, {%8,%9}, {%0,%1,%2,%3};" \
        : "+r"((acc)[0]), "+r"((acc)[1]), "+r"((acc)[2]), "+r"((acc)[3]) \
        : "r"((a).x), "r"((a).y), "r"((a).z), "r"((a).w), "r"((b).x), "r"((b).y))

__global__ void k_init() { if (threadIdx.x < 8) g_absmax[threadIdx.x] = 0.0f; }

// ---- one kernel: absmax of all 4 inputs ----
__device__ __forceinline__ void absmax_seg(const float* __restrict__ t, size_t n4, int slot) {
    float m = 0.0f;
    size_t i = (size_t)blockIdx.x * blockDim.x + threadIdx.x;
    size_t st = (size_t)gridDim.x * blockDim.x;
    const float4* t4 = (const float4*)t;
    for (; i < n4; i += st) {
        float4 v = t4[i];
        m = fmaxf(m, fmaxf(fmaxf(fabsf(v.x), fabsf(v.y)), fmaxf(fabsf(v.z), fabsf(v.w))));
    }
    #pragma unroll
    for (int o = 16; o; o >>= 1) m = fmaxf(m, __shfl_xor_sync(0xffffffffu, m, o));
    if ((threadIdx.x & 31) == 0) atomicMaxPosF(&g_absmax[slot], m);
}
__global__ void k_absmax_all(const float* __restrict__ x, const float* __restrict__ wg,
                             const float* __restrict__ wu, const float* __restrict__ wd) {
    absmax_seg(x,  (size_t)TOKENS * DMODEL / 4, 0);
    absmax_seg(wg, (size_t)HIDDEN * DMODEL / 4, 1);
    absmax_seg(wu, (size_t)HIDDEN * DMODEL / 4, 2);
    absmax_seg(wd, (size_t)DMODEL * HIDDEN / 4, 3);
}

// ---- pack A operand into m16n8k32 fragment order (coalesced) ----
// thread = (row, k32): reads 32 consecutive floats, writes 8 words into frag layout
// NOTE: requires srcStride % 4 == 0 (all A sources are 4096 or 10944)
__global__ void k_packA(const float* __restrict__ src, int8* __restrict__ dst,
                        int rows, int nK32, int srcStride, int Kvalid, int slot) {
    const float s = get_scale(slot);
    uint32_t* d32 = (uint32_t*)dst;
    size_t total = (size_t)rows * nK32;
    for (size_t i = (size_t)blockIdx.x * blockDim.x + threadIdx.x; i < total;
         i += (size_t)gridDim.x * blockDim.x) {
        int row = (int)(i % rows);
        int k32 = (int)(i / rows);
        int kb0 = k32 * 32;
        float f[32];
        if (kb0 + 32 <= Kvalid) {
            load32(src + (size_t)row * srcStride + kb0, f, true);
        } else {
            #pragma unroll
            for (int j = 0; j < 32; j++)
                f[j] = (kb0 + j < Kvalid) ? __ldg(src + (size_t)row * srcStride + kb0 + j) : 0.0f;
        }
        int mtile = row >> 7, rr = row & 127;
        int m16 = rr >> 4, g = rr & 7, rb = (rr >> 3) & 1;
        uint32_t* base = d32 + (size_t)(mtile * nK32 + k32) * 1024 + m16 * 128 + 16 * g + rb;
        #pragma unroll
        for (int t = 0; t < 4; t++)
            #pragma unroll
            for (int kh = 0; kh < 2; kh++) {
                int kb = kh * 16 + t * 4;
                base[4 * t + 2 * kh] = pack4(f[kb], f[kb + 1], f[kb + 2], f[kb + 3], s);
            }
    }
}

// ---- pack B operand into fragment order (coalesced, alignment-safe) ----
// requires srcStride % 2 == 0 (4096, 10922 both even)
__global__ void k_packB(const float* __restrict__ src, int8* __restrict__ dst,
                        int rows, int nK32, int srcStride, int Nvalid, int Kvalid, int slot) {
    const float s = get_scale(slot);
    uint32_t* d32 = (uint32_t*)dst;
    size_t total = (size_t)rows * nK32;
    for (size_t i = (size_t)blockIdx.x * blockDim.x + threadIdx.x; i < total;
         i += (size_t)gridDim.x * blockDim.x) {
        int n = (int)(i % rows);
        int k32 = (int)(i / rows);
        int kb0 = k32 * 32;
        uint32_t out[8];
        if (n < Nvalid) {
            float f[32];
            size_t off = (size_t)n * srcStride + kb0;
            if (kb0 + 32 <= Kvalid) {
                load32(src + off, f, (off & 3) == 0);
            } else {
                #pragma unroll
                for (int j = 0; j < 32; j++)
                    f[j] = (kb0 + j < Kvalid) ? __ldg(src + off + j) : 0.0f;
            }
            #pragma unroll
            for (int t = 0; t < 4; t++)
                #pragma unroll
                for (int reg = 0; reg < 2; reg++) {
                    int kb = reg * 16 + t * 4;
                    out[2 * t + reg] = pack4(f[kb], f[kb + 1], f[kb + 2], f[kb + 3], s);
                }
        } else {
            #pragma unroll
            for (int j = 0; j < 8; j++) out[j] = 0;
        }
        int ntile = n >> 7, nr = n & 127;
        int n8 = nr >> 3, g = nr & 7;
        uint32_t* base = d32 + (size_t)(ntile * nK32 + k32) * 1024 + n8 * 64 + 8 * g;
        *(uint4*)base = *(const uint4*)&out[0];
        *(uint4*)(base + 4) = *(const uint4*)&out[4];
    }
}

// ---- act = silu(q(gate)) * q(up) in place into gate; absmax -> slot 6 ----
// runs over the PADDED extent; pad entries are 0 -> stay 0, don't affect absmax
__global__ void k_act(float* __restrict__ gate, const float* __restrict__ up, size_t n4) {
    float sg = get_scale(4), su = get_scale(5);
    float m = 0.0f;
    size_t i = (size_t)blockIdx.x * blockDim.x + threadIdx.x;
    size_t st = (size_t)gridDim.x * blockDim.x;
    float4* g4 = (float4*)gate;
    const float4* u4 = (const float4*)up;
    for (; i < n4; i += st) {
        float4 gv = g4[i];
        float4 uv = u4[i];
        float* gp = (float*)&gv;
        const float* uq4 = (const float*)&uv;
        #pragma unroll
        for (int k = 0; k < 4; k++) {
            float gq = quant_round(gp[k], sg) * sg;
            float uq = quant_round(uq4[k], su) * su;
            float a = gq * (1.0f / (1.0f + expf(-gq))) * uq;
            gp[k] = a;
            m = fmaxf(m, fabsf(a));
        }
        g4[i] = gv;
    }
    #pragma unroll
    for (int o = 16; o; o >>= 1) m = fmaxf(m, __shfl_xor_sync(0xffffffffu, m, o));
    if ((threadIdx.x & 31) == 0) atomicMaxPosF(&g_absmax[6], m);
}

// ---------------- IMMA GEMM ----------------
// A frag-packed [mtile][k32][m16][lane]x16B, B frag-packed [ntile][k32][n8][lane]x8B
template<bool DO_AMAX>
__global__ void __launch_bounds__(256, 2)
k_gemm(const int8* __restrict__ A, const int8* __restrict__ B,
       const float* __restrict__ bias, float* __restrict__ C,
       int nK32, int Nvalid, int Cstride, int sa, int sb, int amax_slot) {
    extern __shared__ __align__(16) char smem[];   // NSTAGE * 16KB (A 8KB + B 8KB)
    const int tid = threadIdx.x, lane = tid & 31, wid = tid >> 5;
    const int wm = wid >> 2, wn = wid & 3;         // warp grid 2 x 4 (64x32 warp tile)
    const int mtile = blockIdx.y, ntile = blockIdx.x;

    const char* Ag = (const char*)A + (size_t)mtile * nK32 * 4096;
    const char* Bg = (const char*)B + (size_t)ntile * nK32 * 4096;
    const int KS = nK32 >> 1;                      // one stage = K=64 = 8KB A + 8KB B

    int acc[4][4][4];
    #pragma unroll
    for (int i = 0; i < 4; i++)
        #pragma unroll
        for (int j = 0; j < 4; j++)
            #pragma unroll
            for (int r = 0; r < 4; r++) acc[i][j][r] = 0;

    const uint32_t sbase = smem_u32(smem);
    const uint32_t co = (uint32_t)tid * 16u;

    auto issue = [&](int st) {
        uint32_t buf = sbase + (uint32_t)(st % NSTAGE) * 16384u;
        const char* ga = Ag + (size_t)st * 8192;
        const char* gb = Bg + (size_t)st * 8192;
        CP_ASYNC16(buf + co,          ga + co);
        CP_ASYNC16(buf + co + 4096,   ga + co + 4096);
        CP_ASYNC16(buf + co + 8192,   gb + co);
        CP_ASYNC16(buf + co + 12288,  gb + co + 4096);
    };

    #pragma unroll
    for (int p = 0; p < NSTAGE - 1; p++) {
        if (p < KS) issue(p);
        CP_COMMIT();
    }

    for (int c = 0; c < KS; c++) {
        CP_WAIT(NSTAGE - 2);
        __syncthreads();
        if (c + NSTAGE - 1 < KS) issue(c + NSTAGE - 1);
        CP_COMMIT();

        const char* bufA = smem + (c % NSTAGE) * 16384;
        const char* bufB = bufA + 8192;
        #pragma unroll
        for (int kk = 0; kk < 2; kk++) {
            int4 av[4];
            int2 bv[4];
            #pragma unroll
            for (int i = 0; i < 4; i++)
                av[i] = *(const int4*)(bufA + (((kk * 8 + wm * 4 + i) * 32 + lane) << 4));
            #pragma unroll
            for (int j = 0; j < 4; j++)
                bv[j] = *(const int2*)(bufB + (((kk * 16 + wn * 4 + j) * 32 + lane) << 3));
            #pragma unroll
            for (int i = 0; i < 4; i++)
                #pragma unroll
                for (int j = 0; j < 4; j++)
                    IMMA(acc[i][j], av[i], bv[j]);
        }
    }

    // epilogue: scale + bias (+ absmax)
    const float sab = get_scale(sa) * get_scale(sb);
    const int g = lane >> 2, t = lane & 3;
    float vmax = 0.0f;
    #pragma unroll
    for (int i = 0; i < 4; i++) {
        int row0 = mtile * 128 + wm * 64 + i * 16 + g;
        #pragma unroll
        for (int j = 0; j < 4; j++) {
            int col = ntile * 128 + wn * 32 + j * 8 + t * 2;
            if (col < Nvalid) {
                float b0 = __ldg(&bias[col]), b1 = __ldg(&bias[col + 1]);
                float2 v0, v1;
                v0.x = fmaf((float)acc[i][j][0], sab, b0);
                v0.y = fmaf((float)acc[i][j][1], sab, b1);
                v1.x = fmaf((float)acc[i][j][2], sab, b0);
                v1.y = fmaf((float)acc[i][j][3], sab, b1);
                *(float2*)(C + (size_t)row0 * Cstride + col) = v0;
                *(float2*)(C + (size_t)(row0 + 8) * Cstride + col) = v1;
                if (DO_AMAX)
                    vmax = fmaxf(vmax, fmaxf(fmaxf(fabsf(v0.x), fabsf(v0.y)),
                                             fmaxf(fabsf(v1.x), fabsf(v1.y))));
            }
        }
    }
    if (DO_AMAX) {
        #pragma unroll
        for (int o = 16; o; o >>= 1) vmax = fmaxf(vmax, __shfl_xor_sync(0xffffffffu, vmax, o));
        if (lane == 0) atomicMaxPosF(&g_absmax[amax_slot], vmax);
    }
}

// ---------------- launch ----------------
extern "C" void kernel_launch(void* const* d_in, const int* in_sizes, int n_in,
                              void* d_out, int out_size) {
    (void)in_sizes; (void)n_in; (void)out_size;
    const float* x  = (const float*)d_in[0];
    const float* wg = (const float*)d_in[1];
    const float* wu = (const float*)d_in[2];
    const float* wd = (const float*)d_in[3];
    const float* bg = (const float*)d_in[4];
    const float* bu = (const float*)d_in[5];
    const float* bd = (const float*)d_in[6];
    float* out = (float*)d_out;

    int8 *pXi, *pGi, *pUi, *pDi, *pAi;
    float *pGate, *pUp;
    cudaGetSymbolAddress((void**)&pXi, g_Xi);
    cudaGetSymbolAddress((void**)&pGi, g_Gi);
    cudaGetSymbolAddress((void**)&pUi, g_Ui);
    cudaGetSymbolAddress((void**)&pDi, g_Di);
    cudaGetSymbolAddress((void**)&pAi, g_Ai);
    cudaGetSymbolAddress((void**)&pGate, g_gate);
    cudaGetSymbolAddress((void**)&pUp, g_up);

    cudaFuncSetAttribute(k_gemm<true>,  cudaFuncAttributeMaxDynamicSharedMemorySize, NSTAGE * 16384);
    cudaFuncSetAttribute(k_gemm<false>, cudaFuncAttributeMaxDynamicSharedMemorySize, NSTAGE * 16384);

    const int RT = 256;
    const int nK32g = DMODEL / 32;   // 128
    const int nK32d = HPADK / 32;    // 342

    // launch order puts gemm<gate> at stream launch index 4 (the one ncu captures)
    k_init<<<1, 8>>>();                                                        // 0
    k_absmax_all<<<2048, RT>>>(x, wg, wu, wd);                                 // 1
    k_packA<<<((size_t)TOKENS * nK32g + RT - 1) / RT, RT>>>(                   // 2
        x, pXi, TOKENS, nK32g, DMODEL, DMODEL, 0);
    k_packB<<<((size_t)HPADN * nK32g + RT - 1) / RT, RT>>>(                    // 3
        wg, pGi, HPADN, nK32g, DMODEL, HIDDEN, DMODEL, 1);
    dim3 g1(HPADN / 128, TOKENS / 128);
    k_gemm<true><<<g1, 256, NSTAGE * 16384>>>(                                 // 4  <- ncu capture
        pXi, pGi, bg, pGate, nK32g, HIDDEN, HPADK, 0, 1, 4);
    k_packB<<<((size_t)HPADN * nK32g + RT - 1) / RT, RT>>>(                    // 5
        wu, pUi, HPADN, nK32g, DMODEL, HIDDEN, DMODEL, 2);
    k_gemm<true><<<g1, 256, NSTAGE * 16384>>>(                                 // 6
        pXi, pUi, bu, pUp, nK32g, HIDDEN, HPADK, 0, 2, 5);
    k_packB<<<((size_t)DMODEL * nK32d + RT - 1) / RT, RT>>>(                   // 7
        wd, pDi, DMODEL, nK32d, HIDDEN, DMODEL, HIDDEN, 3);
    k_act<<<2048, RT>>>(pGate, pUp, (size_t)TOKENS * HPADK / 4);               // 8
    k_packA<<<((size_t)TOKENS * nK32d + RT - 1) / RT, RT>>>(                   // 9
        pGate, pAi, TOKENS, nK32d, HPADK, HPADK, 6);
    dim3 g2(DMODEL / 128, TOKENS / 128);
    k_gemm<false><<<g2, 256, NSTAGE * 16384>>>(                                // 10
        pAi, pDi, bd, out, nK32d, DMODEL, DMODEL, 6, 3, -1);
}

// round 7
// speedup vs baseline: 1.4388x; 1.2348x over previous
#include <cuda_runtime.h>
#include <cuda_bf16.h>
#include <cstdint>
#include <math.h>

#define TOKENS 4096
#define DMODEL 4096
#define HIDDEN 10922
#define HPADN  11008   // hidden padded to 128 (B rows / output cols for gate & up)
#define HPADK  10944   // hidden padded to 64; also activation buffer stride (mult of 4)
#define NSTAGE 4

typedef signed char int8;

// ---------------- device scratch ----------------
__device__ __align__(256) int8 g_Xi[(size_t)TOKENS * DMODEL];    // A frag-packed (imma)
__device__ __align__(256) int8 g_Ui[(size_t)HPADN * DMODEL];     // B frag-packed (imma)
__device__ __align__(256) int8 g_Di[(size_t)DMODEL * HPADK];     // B frag-packed (imma)
__device__ __align__(256) int8 g_Ai[(size_t)TOKENS * HPADK];     // A frag-packed (imma)
__device__ __align__(256) __nv_bfloat16 g_Xbf[(size_t)TOKENS * DMODEL];  // A frag (hmma)
__device__ __align__(256) __nv_bfloat16 g_Gbf[(size_t)HPADN * DMODEL];   // B frag (hmma)
__device__ __align__(16) float g_gate[(size_t)TOKENS * HPADK];   // padded stride
__device__ __align__(16) float g_up  [(size_t)TOKENS * HPADK];   // padded stride
__device__ float g_absmax[8];   // 0:x 1:wg 2:wu 3:wd 4:gate 5:up 6:act

// ---------------- helpers ----------------
__device__ __forceinline__ void atomicMaxPosF(float* a, float v) {
    atomicMax((unsigned int*)a, __float_as_uint(v));
}
__device__ __forceinline__ float quant_round(float x, float s) {
    float r = rintf(__fdiv_rn(x, s));
    return fminf(fmaxf(r, -127.0f), 127.0f);
}
__device__ __forceinline__ float get_scale(int slot) {
    return fmaxf(__fdiv_rn(g_absmax[slot], 127.0f), 1e-8f);
}
__device__ __forceinline__ uint32_t smem_u32(const void* p) {
    uint32_t a;
    asm("{ .reg .u64 t; cvta.to.shared.u64 t, %1; cvt.u32.u64 %0, t; }" : "=r"(a) : "l"(p));
    return a;
}
__device__ __forceinline__ uint32_t pack4(float a, float b, float c, float d, float s) {
    uint32_t qa = (uint32_t)(uint8_t)(int8)(int)quant_round(a, s);
    uint32_t qb = (uint32_t)(uint8_t)(int8)(int)quant_round(b, s);
    uint32_t qc = (uint32_t)(uint8_t)(int8)(int)quant_round(c, s);
    uint32_t qd = (uint32_t)(uint8_t)(int8)(int)quant_round(d, s);
    return qa | (qb << 8) | (qc << 16) | (qd << 24);
}
__device__ __forceinline__ uint32_t bf2(float a, float b, float s) {
    __nv_bfloat16 lo = __float2bfloat16_rn(quant_round(a, s));
    __nv_bfloat16 hi = __float2bfloat16_rn(quant_round(b, s));
    return (uint32_t)__bfloat16_as_ushort(lo) | ((uint32_t)__bfloat16_as_ushort(hi) << 16);
}
// load 32 consecutive floats; p at least 8B-aligned; a16: 16B-aligned
__device__ __forceinline__ void load32(const float* __restrict__ p, float* f, bool a16) {
    if (a16) {
        #pragma unroll
        for (int q = 0; q < 8; q++) *(float4*)&f[q * 4] = __ldg((const float4*)p + q);
    } else {
        #pragma unroll
        for (int q = 0; q < 16; q++) *(float2*)&f[q * 2] = __ldg((const float2*)p + q);
    }
}
#define CP_ASYNC16(dst, src) \
    asm volatile("cp.async.cg.shared.global [%0], [%1], 16;" :: "r"(dst), "l"(src))
#define CP_COMMIT() asm volatile("cp.async.commit_group;")
#define CP_WAIT(n)  asm volatile("cp.async.wait_group %0;" :: "n"(n))

#define IMMA(acc, a, b) \
    asm volatile("mma.sync.aligned.m16n8k32.row.col.s32.s8.s8.s32 " \
        "{%0,%1,%2,%3}, {%4,%5,%6,%7}, {%8,%9}, {%0,%1,%2,%3};" \
        : "+r"((acc)[0]), "+r"((acc)[1]), "+r"((acc)[2]), "+r"((acc)[3]) \
        : "r"((a).x), "r"((a).y), "r"((a).z), "r"((a).w), "r"((b).x), "r"((b).y))

#define HMMA(acc, a, b) \
    asm volatile("mma.sync.aligned.m16n8k16.row.col.f32.bf16.bf16.f32 " \
        "{%0,%1,%2,%3}, {%4,%5,%6,%7}, {%8,%9}, {%0,%1,%2,%3};" \
        : "+f"((acc)[0]), "+f"((acc)[1]), "+f"((acc)[2]), "+f"((acc)[3]) \
        : "r"((a).x), "r"((a).y), "r"((a).z), "r"((a).w), "r"((b).x), "r"((b).y))

__global__ void k_init() { if (threadIdx.x < 8) g_absmax[threadIdx.x] = 0.0f; }

// ---- one kernel: absmax of all 4 inputs ----
__device__ __forceinline__ void absmax_seg(const float* __restrict__ t, size_t n4, int slot) {
    float m = 0.0f;
    size_t i = (size_t)blockIdx.x * blockDim.x + threadIdx.x;
    size_t st = (size_t)gridDim.x * blockDim.x;
    const float4* t4 = (const float4*)t;
    for (; i < n4; i += st) {
        float4 v = t4[i];
        m = fmaxf(m, fmaxf(fmaxf(fabsf(v.x), fabsf(v.y)), fmaxf(fabsf(v.z), fabsf(v.w))));
    }
    #pragma unroll
    for (int o = 16; o; o >>= 1) m = fmaxf(m, __shfl_xor_sync(0xffffffffu, m, o));
    if ((threadIdx.x & 31) == 0) atomicMaxPosF(&g_absmax[slot], m);
}
__global__ void k_absmax_all(const float* __restrict__ x, const float* __restrict__ wg,
                             const float* __restrict__ wu, const float* __restrict__ wd) {
    absmax_seg(x,  (size_t)TOKENS * DMODEL / 4, 0);
    absmax_seg(wg, (size_t)HIDDEN * DMODEL / 4, 1);
    absmax_seg(wu, (size_t)HIDDEN * DMODEL / 4, 2);
    absmax_seg(wd, (size_t)DMODEL * HIDDEN / 4, 3);
}

// ======== int8 IMMA packs (m16n8k32) ========
__global__ void k_packA(const float* __restrict__ src, int8* __restrict__ dst,
                        int rows, int nK32, int srcStride, int Kvalid, int slot) {
    const float s = get_scale(slot);
    uint32_t* d32 = (uint32_t*)dst;
    size_t total = (size_t)rows * nK32;
    for (size_t i = (size_t)blockIdx.x * blockDim.x + threadIdx.x; i < total;
         i += (size_t)gridDim.x * blockDim.x) {
        int row = (int)(i % rows);
        int k32 = (int)(i / rows);
        int kb0 = k32 * 32;
        float f[32];
        if (kb0 + 32 <= Kvalid) {
            load32(src + (size_t)row * srcStride + kb0, f, true);
        } else {
            #pragma unroll
            for (int j = 0; j < 32; j++)
                f[j] = (kb0 + j < Kvalid) ? __ldg(src + (size_t)row * srcStride + kb0 + j) : 0.0f;
        }
        int mtile = row >> 7, rr = row & 127;
        int m16 = rr >> 4, g = rr & 7, rb = (rr >> 3) & 1;
        uint32_t* base = d32 + (size_t)(mtile * nK32 + k32) * 1024 + m16 * 128 + 16 * g + rb;
        #pragma unroll
        for (int t = 0; t < 4; t++)
            #pragma unroll
            for (int kh = 0; kh < 2; kh++) {
                int kb = kh * 16 + t * 4;
                base[4 * t + 2 * kh] = pack4(f[kb], f[kb + 1], f[kb + 2], f[kb + 3], s);
            }
    }
}

__global__ void k_packB(const float* __restrict__ src, int8* __restrict__ dst,
                        int rows, int nK32, int srcStride, int Nvalid, int Kvalid, int slot) {
    const float s = get_scale(slot);
    uint32_t* d32 = (uint32_t*)dst;
    size_t total = (size_t)rows * nK32;
    for (size_t i = (size_t)blockIdx.x * blockDim.x + threadIdx.x; i < total;
         i += (size_t)gridDim.x * blockDim.x) {
        int n = (int)(i % rows);
        int k32 = (int)(i / rows);
        int kb0 = k32 * 32;
        uint32_t out[8];
        if (n < Nvalid) {
            float f[32];
            size_t off = (size_t)n * srcStride + kb0;
            if (kb0 + 32 <= Kvalid) {
                load32(src + off, f, (off & 3) == 0);
            } else {
                #pragma unroll
                for (int j = 0; j < 32; j++)
                    f[j] = (kb0 + j < Kvalid) ? __ldg(src + off + j) : 0.0f;
            }
            #pragma unroll
            for (int t = 0; t < 4; t++)
                #pragma unroll
                for (int reg = 0; reg < 2; reg++) {
                    int kb = reg * 16 + t * 4;
                    out[2 * t + reg] = pack4(f[kb], f[kb + 1], f[kb + 2], f[kb + 3], s);
                }
        } else {
            #pragma unroll
            for (int j = 0; j < 8; j++) out[j] = 0;
        }
        int ntile = n >> 7, nr = n & 127;
        int n8 = nr >> 3, g = nr & 7;
        uint32_t* base = d32 + (size_t)(ntile * nK32 + k32) * 1024 + n8 * 64 + 8 * g;
        *(uint4*)base = *(const uint4*)&out[0];
        *(uint4*)(base + 4) = *(const uint4*)&out[4];
    }
}

// ======== bf16 HMMA packs (m16n8k16) ========
// A frag layout: [mtile][k16][m16][lane]x16B (regs a0..a3)
__global__ void k_packA_bf16(const float* __restrict__ src, __nv_bfloat16* __restrict__ dst,
                             int rows, int nK32, int srcStride, int Kvalid, int slot) {
    const float s = get_scale(slot);
    uint32_t* d32 = (uint32_t*)dst;
    const int nK16 = nK32 * 2;
    size_t total = (size_t)rows * nK32;
    for (size_t i = (size_t)blockIdx.x * blockDim.x + threadIdx.x; i < total;
         i += (size_t)gridDim.x * blockDim.x) {
        int row = (int)(i % rows);
        int k32 = (int)(i / rows);
        int kb0 = k32 * 32;
        float f[32];
        if (kb0 + 32 <= Kvalid) {
            load32(src + (size_t)row * srcStride + kb0, f, true);
        } else {
            #pragma unroll
            for (int j = 0; j < 32; j++)
                f[j] = (kb0 + j < Kvalid) ? __ldg(src + (size_t)row * srcStride + kb0 + j) : 0.0f;
        }
        int mtile = row >> 7, rr = row & 127;
        int m16 = rr >> 4, g = rr & 7, rb = (rr >> 3) & 1;
        #pragma unroll
        for (int kh = 0; kh < 2; kh++) {
            int k16 = k32 * 2 + kh;
            uint32_t* base = d32 + (size_t)(mtile * nK16 + k16) * 1024 + m16 * 128 + 16 * g;
            const float* fk = f + kh * 16;
            #pragma unroll
            for (int t = 0; t < 4; t++) {
                base[4 * t + rb]     = bf2(fk[2 * t],     fk[2 * t + 1], s);
                base[4 * t + rb + 2] = bf2(fk[8 + 2 * t], fk[9 + 2 * t], s);
            }
        }
    }
}

// B frag layout: [ntile][k16][n8][lane]x8B (regs b0,b1)
__global__ void k_packB_bf16(const float* __restrict__ src, __nv_bfloat16* __restrict__ dst,
                             int rows, int nK32, int srcStride, int Nvalid, int Kvalid, int slot) {
    const float s = get_scale(slot);
    uint32_t* d32 = (uint32_t*)dst;
    const int nK16 = nK32 * 2;
    size_t total = (size_t)rows * nK32;
    for (size_t i = (size_t)blockIdx.x * blockDim.x + threadIdx.x; i < total;
         i += (size_t)gridDim.x * blockDim.x) {
        int n = (int)(i % rows);
        int k32 = (int)(i / rows);
        int kb0 = k32 * 32;
        float f[32];
        if (n < Nvalid) {
            size_t off = (size_t)n * srcStride + kb0;
            if (kb0 + 32 <= Kvalid) {
                load32(src + off, f, (off & 3) == 0);
            } else {
                #pragma unroll
                for (int j = 0; j < 32; j++)
                    f[j] = (kb0 + j < Kvalid) ? __ldg(src + off + j) : 0.0f;
            }
        } else {
            #pragma unroll
            for (int j = 0; j < 32; j++) f[j] = 0.0f;
        }
        int ntile = n >> 7, nr = n & 127;
        int n8 = nr >> 3, g = nr & 7;
        #pragma unroll
        for (int kh = 0; kh < 2; kh++) {
            int k16 = k32 * 2 + kh;
            uint32_t* base = d32 + (size_t)(ntile * nK16 + k16) * 1024 + n8 * 64 + 8 * g;
            const float* fk = f + kh * 16;
            #pragma unroll
            for (int t = 0; t < 4; t++) {
                base[2 * t]     = bf2(fk[2 * t],     fk[2 * t + 1], s);
                base[2 * t + 1] = bf2(fk[8 + 2 * t], fk[9 + 2 * t], s);
            }
        }
    }
}

// ---- act = silu(q(gate)) * q(up) in place into gate; absmax -> slot 6 ----
__global__ void k_act(float* __restrict__ gate, const float* __restrict__ up, size_t n4) {
    float sg = get_scale(4), su = get_scale(5);
    float m = 0.0f;
    size_t i = (size_t)blockIdx.x * blockDim.x + threadIdx.x;
    size_t st = (size_t)gridDim.x * blockDim.x;
    float4* g4 = (float4*)gate;
    const float4* u4 = (const float4*)up;
    for (; i < n4; i += st) {
        float4 gv = g4[i];
        float4 uv = u4[i];
        float* gp = (float*)&gv;
        const float* uq4 = (const float*)&uv;
        #pragma unroll
        for (int k = 0; k < 4; k++) {
            float gq = quant_round(gp[k], sg) * sg;
            float uq = quant_round(uq4[k], su) * su;
            float a = gq * (1.0f / (1.0f + expf(-gq))) * uq;
            gp[k] = a;
            m = fmaxf(m, fabsf(a));
        }
        g4[i] = gv;
    }
    #pragma unroll
    for (int o = 16; o; o >>= 1) m = fmaxf(m, __shfl_xor_sync(0xffffffffu, m, o));
    if ((threadIdx.x & 31) == 0) atomicMaxPosF(&g_absmax[6], m);
}

// ---------------- shared GEMM body (IMMA int8 or HMMA bf16) ----------------
// One stage = 16KB (A 8KB + B 8KB). IMMA: stage = K64. HMMA: stage = K32.
// Per-tile operand stride = KS * 8192 bytes (A and B identical).
template<bool DO_AMAX, bool BF16>
__global__ void __launch_bounds__(256, 2)
k_gemm(const void* __restrict__ A, const void* __restrict__ B,
       const float* __restrict__ bias, float* __restrict__ C,
       int nK32, int Nvalid, int Cstride, int sa, int sb, int amax_slot) {
    extern __shared__ __align__(16) char smem[];   // NSTAGE * 16KB
    const int tid = threadIdx.x, lane = tid & 31, wid = tid >> 5;
    const int wm = wid >> 2, wn = wid & 3;         // warp grid 2 x 4 (64x32 warp tile)
    const int mtile = blockIdx.y, ntile = blockIdx.x;

    const int KS = BF16 ? nK32 : (nK32 >> 1);      // stages
    const char* Ag = (const char*)A + (size_t)mtile * KS * 8192;   // FIX: KS*8192, both modes
    const char* Bg = (const char*)B + (size_t)ntile * KS * 8192;

    int   iacc[4][4][4];
    float facc[4][4][4];
    #pragma unroll
    for (int i = 0; i < 4; i++)
        #pragma unroll
        for (int j = 0; j < 4; j++)
            #pragma unroll
            for (int r = 0; r < 4; r++) { iacc[i][j][r] = 0; facc[i][j][r] = 0.0f; }

    const uint32_t sbase = smem_u32(smem);
    const uint32_t co = (uint32_t)tid * 16u;

    auto issue = [&](int st) {
        uint32_t buf = sbase + (uint32_t)(st % NSTAGE) * 16384u;
        const char* ga = Ag + (size_t)st * 8192;
        const char* gb = Bg + (size_t)st * 8192;
        CP_ASYNC16(buf + co,          ga + co);
        CP_ASYNC16(buf + co + 4096,   ga + co + 4096);
        CP_ASYNC16(buf + co + 8192,   gb + co);
        CP_ASYNC16(buf + co + 12288,  gb + co + 4096);
    };

    #pragma unroll
    for (int p = 0; p < NSTAGE - 1; p++) {
        if (p < KS) issue(p);
        CP_COMMIT();
    }

    for (int c = 0; c < KS; c++) {
        CP_WAIT(NSTAGE - 2);
        __syncthreads();
        if (c + NSTAGE - 1 < KS) issue(c + NSTAGE - 1);
        CP_COMMIT();

        const char* bufA = smem + (c % NSTAGE) * 16384;
        const char* bufB = bufA + 8192;
        #pragma unroll
        for (int kk = 0; kk < 2; kk++) {
            int4 av[4];
            int2 bv[4];
            #pragma unroll
            for (int i = 0; i < 4; i++)
                av[i] = *(const int4*)(bufA + (((kk * 8 + wm * 4 + i) * 32 + lane) << 4));
            #pragma unroll
            for (int j = 0; j < 4; j++)
                bv[j] = *(const int2*)(bufB + (((kk * 16 + wn * 4 + j) * 32 + lane) << 3));
            #pragma unroll
            for (int i = 0; i < 4; i++)
                #pragma unroll
                for (int j = 0; j < 4; j++) {
                    if (BF16) HMMA(facc[i][j], av[i], bv[j]);
                    else      IMMA(iacc[i][j], av[i], bv[j]);
                }
        }
    }

    // epilogue: scale + bias (+ absmax)
    const float sab = get_scale(sa) * get_scale(sb);
    const int g = lane >> 2, t = lane & 3;
    float vmax = 0.0f;
    #pragma unroll
    for (int i = 0; i < 4; i++) {
        int row0 = mtile * 128 + wm * 64 + i * 16 + g;
        #pragma unroll
        for (int j = 0; j < 4; j++) {
            int col = ntile * 128 + wn * 32 + j * 8 + t * 2;
            if (col < Nvalid) {
                float a0 = BF16 ? facc[i][j][0] : (float)iacc[i][j][0];
                float a1 = BF16 ? facc[i][j][1] : (float)iacc[i][j][1];
                float a2 = BF16 ? facc[i][j][2] : (float)iacc[i][j][2];
                float a3 = BF16 ? facc[i][j][3] : (float)iacc[i][j][3];
                float b0 = __ldg(&bias[col]), b1 = __ldg(&bias[col + 1]);
                float2 v0, v1;
                v0.x = fmaf(a0, sab, b0);
                v0.y = fmaf(a1, sab, b1);
                v1.x = fmaf(a2, sab, b0);
                v1.y = fmaf(a3, sab, b1);
                *(float2*)(C + (size_t)row0 * Cstride + col) = v0;
                *(float2*)(C + (size_t)(row0 + 8) * Cstride + col) = v1;
                if (DO_AMAX)
                    vmax = fmaxf(vmax, fmaxf(fmaxf(fabsf(v0.x), fabsf(v0.y)),
                                             fmaxf(fabsf(v1.x), fabsf(v1.y))));
            }
        }
    }
    if (DO_AMAX) {
        #pragma unroll
        for (int o = 16; o; o >>= 1) vmax = fmaxf(vmax, __shfl_xor_sync(0xffffffffu, vmax, o));
        if (lane == 0) atomicMaxPosF(&g_absmax[amax_slot], vmax);
    }
}

// ---------------- launch ----------------
extern "C" void kernel_launch(void* const* d_in, const int* in_sizes, int n_in,
                              void* d_out, int out_size) {
    (void)in_sizes; (void)n_in; (void)out_size;
    const float* x  = (const float*)d_in[0];
    const float* wg = (const float*)d_in[1];
    const float* wu = (const float*)d_in[2];
    const float* wd = (const float*)d_in[3];
    const float* bg = (const float*)d_in[4];
    const float* bu = (const float*)d_in[5];
    const float* bd = (const float*)d_in[6];
    float* out = (float*)d_out;

    int8 *pXi, *pUi, *pDi, *pAi;
    __nv_bfloat16 *pXbf, *pGbf;
    float *pGate, *pUp;
    cudaGetSymbolAddress((void**)&pXi, g_Xi);
    cudaGetSymbolAddress((void**)&pUi, g_Ui);
    cudaGetSymbolAddress((void**)&pDi, g_Di);
    cudaGetSymbolAddress((void**)&pAi, g_Ai);
    cudaGetSymbolAddress((void**)&pXbf, g_Xbf);
    cudaGetSymbolAddress((void**)&pGbf, g_Gbf);
    cudaGetSymbolAddress((void**)&pGate, g_gate);
    cudaGetSymbolAddress((void**)&pUp, g_up);

    cudaFuncSetAttribute(k_gemm<true, false>,  cudaFuncAttributeMaxDynamicSharedMemorySize, NSTAGE * 16384);
    cudaFuncSetAttribute(k_gemm<false, false>, cudaFuncAttributeMaxDynamicSharedMemorySize, NSTAGE * 16384);
    cudaFuncSetAttribute(k_gemm<true, true>,   cudaFuncAttributeMaxDynamicSharedMemorySize, NSTAGE * 16384);

    const int RT = 256;
    const int nK32g = DMODEL / 32;   // 128
    const int nK32d = HPADK / 32;    // 342

    dim3 g1(HPADN / 128, TOKENS / 128);
    dim3 g2(DMODEL / 128, TOKENS / 128);

    // capture is launch index 5 (-s 5 -c 1) -> gate HMMA GEMM
    k_init<<<1, 8>>>();                                                        // 0
    k_absmax_all<<<2048, RT>>>(x, wg, wu, wd);                                 // 1
    k_packA_bf16<<<((size_t)TOKENS * nK32g + RT - 1) / RT, RT>>>(              // 2
        x, pXbf, TOKENS, nK32g, DMODEL, DMODEL, 0);
    k_packB_bf16<<<((size_t)HPADN * nK32g + RT - 1) / RT, RT>>>(               // 3
        wg, pGbf, HPADN, nK32g, DMODEL, HIDDEN, DMODEL, 1);
    k_packA<<<((size_t)TOKENS * nK32g + RT - 1) / RT, RT>>>(                   // 4
        x, pXi, TOKENS, nK32g, DMODEL, DMODEL, 0);
    k_gemm<true, true><<<g1, 256, NSTAGE * 16384>>>(                           // 5  <- ncu capture
        pXbf, pGbf, bg, pGate, nK32g, HIDDEN, HPADK, 0, 1, 4);
    k_packB<<<((size_t)HPADN * nK32g + RT - 1) / RT, RT>>>(                    // 6
        wu, pUi, HPADN, nK32g, DMODEL, HIDDEN, DMODEL, 2);
    k_gemm<true, false><<<g1, 256, NSTAGE * 16384>>>(                          // 7
        pXi, pUi, bu, pUp, nK32g, HIDDEN, HPADK, 0, 2, 5);
    k_packB<<<((size_t)DMODEL * nK32d + RT - 1) / RT, RT>>>(                   // 8
        wd, pDi, DMODEL, nK32d, HIDDEN, DMODEL, HIDDEN, 3);
    k_act<<<2048, RT>>>(pGate, pUp, (size_t)TOKENS * HPADK / 4);               // 9
    k_packA<<<((size_t)TOKENS * nK32d + RT - 1) / RT, RT>>>(                   // 10
        pGate, pAi, TOKENS, nK32d, HPADK, HPADK, 6);
    k_gemm<false, false><<<g2, 256, NSTAGE * 16384>>>(                         // 11
        pAi, pDi, bd, out, nK32d, DMODEL, DMODEL, 6, 3, -1);
}

// round 8
// speedup vs baseline: 2.8858x; 2.0057x over previous
#include <cuda_runtime.h>
#include <cuda_bf16.h>
#include <cstdint>
#include <math.h>

#define TOKENS 4096
#define DMODEL 4096
#define HIDDEN 10922
#define HPADN  11008   // hidden padded to 128 (B rows / output cols for gate & up)
#define HPADK  10944   // hidden padded to 64; also activation buffer stride (mult of 4)
#define NSTAGE 4

// ---------------- device scratch (all bf16 frag-packed for HMMA) ----------------
__device__ __align__(256) __nv_bfloat16 g_Xbf[(size_t)TOKENS * DMODEL];   // A frags
__device__ __align__(256) __nv_bfloat16 g_Gbf[(size_t)HPADN * DMODEL];    // B frags
__device__ __align__(256) __nv_bfloat16 g_Ubf[(size_t)HPADN * DMODEL];    // B frags
__device__ __align__(256) __nv_bfloat16 g_Dbf[(size_t)DMODEL * HPADK];    // B frags
__device__ __align__(256) __nv_bfloat16 g_Abf[(size_t)TOKENS * HPADK];    // A frags
__device__ __align__(16) float g_gate[(size_t)TOKENS * HPADK];   // padded stride
__device__ __align__(16) float g_up  [(size_t)TOKENS * HPADK];   // padded stride
__device__ float g_absmax[8];   // 0:x 1:wg 2:wu 3:wd 4:gate 5:up 6:act

// ---------------- helpers ----------------
__device__ __forceinline__ void atomicMaxPosF(float* a, float v) {
    atomicMax((unsigned int*)a, __float_as_uint(v));
}
__device__ __forceinline__ float quant_round(float x, float s) {
    float r = rintf(__fdiv_rn(x, s));
    return fminf(fmaxf(r, -127.0f), 127.0f);
}
__device__ __forceinline__ float get_scale(int slot) {
    return fmaxf(__fdiv_rn(g_absmax[slot], 127.0f), 1e-8f);
}
__device__ __forceinline__ uint32_t smem_u32(const void* p) {
    uint32_t a;
    asm("{ .reg .u64 t; cvta.to.shared.u64 t, %1; cvt.u32.u64 %0, t; }" : "=r"(a) : "l"(p));
    return a;
}
__device__ __forceinline__ uint32_t bf2(float a, float b, float s) {
    __nv_bfloat16 lo = __float2bfloat16_rn(quant_round(a, s));
    __nv_bfloat16 hi = __float2bfloat16_rn(quant_round(b, s));
    return (uint32_t)__bfloat16_as_ushort(lo) | ((uint32_t)__bfloat16_as_ushort(hi) << 16);
}
// load 32 consecutive floats; p at least 8B-aligned; a16: 16B-aligned
__device__ __forceinline__ void load32(const float* __restrict__ p, float* f, bool a16) {
    if (a16) {
        #pragma unroll
        for (int q = 0; q < 8; q++) *(float4*)&f[q * 4] = __ldg((const float4*)p + q);
    } else {
        #pragma unroll
        for (int q = 0; q < 16; q++) *(float2*)&f[q * 2] = __ldg((const float2*)p + q);
    }
}
#define CP_ASYNC16(dst, src) \
    asm volatile("cp.async.cg.shared.global [%0], [%1], 16;" :: "r"(dst), "l"(src))
#define CP_COMMIT() asm volatile("cp.async.commit_group;")
#define CP_WAIT(n)  asm volatile("cp.async.wait_group %0;" :: "n"(n))

#define HMMA(acc, a, b) \
    asm volatile("mma.sync.aligned.m16n8k16.row.col.f32.bf16.bf16.f32 " \
        "{%0,%1,%2,%3}, {%4,%5,%6,%7}, {%8,%9}, {%0,%1,%2,%3};" \
        : "+f"((acc)[0]), "+f"((acc)[1]), "+f"((acc)[2]), "+f"((acc)[3]) \
        : "r"((a).x), "r"((a).y), "r"((a).z), "r"((a).w), "r"((b).x), "r"((b).y))

__global__ void k_init() { if (threadIdx.x < 8) g_absmax[threadIdx.x] = 0.0f; }

// ---- one kernel: absmax of all 4 inputs ----
__device__ __forceinline__ void absmax_seg(const float* __restrict__ t, size_t n4, int slot) {
    float m = 0.0f;
    size_t i = (size_t)blockIdx.x * blockDim.x + threadIdx.x;
    size_t st = (size_t)gridDim.x * blockDim.x;
    const float4* t4 = (const float4*)t;
    for (; i < n4; i += st) {
        float4 v = t4[i];
        m = fmaxf(m, fmaxf(fmaxf(fabsf(v.x), fabsf(v.y)), fmaxf(fabsf(v.z), fabsf(v.w))));
    }
    #pragma unroll
    for (int o = 16; o; o >>= 1) m = fmaxf(m, __shfl_xor_sync(0xffffffffu, m, o));
    if ((threadIdx.x & 31) == 0) atomicMaxPosF(&g_absmax[slot], m);
}
__global__ void k_absmax_all(const float* __restrict__ x, const float* __restrict__ wg,
                             const float* __restrict__ wu, const float* __restrict__ wd) {
    absmax_seg(x,  (size_t)TOKENS * DMODEL / 4, 0);
    absmax_seg(wg, (size_t)HIDDEN * DMODEL / 4, 1);
    absmax_seg(wu, (size_t)HIDDEN * DMODEL / 4, 2);
    absmax_seg(wd, (size_t)DMODEL * HIDDEN / 4, 3);
}

// ======== bf16 HMMA packs (m16n8k16) ========
// A frag layout: [mtile][k16][m16][lane]x16B (regs a0..a3)
__global__ void k_packA_bf16(const float* __restrict__ src, __nv_bfloat16* __restrict__ dst,
                             int rows, int nK32, int srcStride, int Kvalid, int slot) {
    const float s = get_scale(slot);
    uint32_t* d32 = (uint32_t*)dst;
    const int nK16 = nK32 * 2;
    size_t total = (size_t)rows * nK32;
    for (size_t i = (size_t)blockIdx.x * blockDim.x + threadIdx.x; i < total;
         i += (size_t)gridDim.x * blockDim.x) {
        int row = (int)(i % rows);
        int k32 = (int)(i / rows);
        int kb0 = k32 * 32;
        float f[32];
        if (kb0 + 32 <= Kvalid) {
            load32(src + (size_t)row * srcStride + kb0, f, true);
        } else {
            #pragma unroll
            for (int j = 0; j < 32; j++)
                f[j] = (kb0 + j < Kvalid) ? __ldg(src + (size_t)row * srcStride + kb0 + j) : 0.0f;
        }
        int mtile = row >> 7, rr = row & 127;
        int m16 = rr >> 4, g = rr & 7, rb = (rr >> 3) & 1;
        #pragma unroll
        for (int kh = 0; kh < 2; kh++) {
            int k16 = k32 * 2 + kh;
            uint32_t* base = d32 + (size_t)(mtile * nK16 + k16) * 1024 + m16 * 128 + 16 * g;
            const float* fk = f + kh * 16;
            #pragma unroll
            for (int t = 0; t < 4; t++) {
                base[4 * t + rb]     = bf2(fk[2 * t],     fk[2 * t + 1], s);
                base[4 * t + rb + 2] = bf2(fk[8 + 2 * t], fk[9 + 2 * t], s);
            }
        }
    }
}

// B frag layout: [ntile][k16][n8][lane]x8B (regs b0,b1); 8 contiguous words per thread
__global__ void k_packB_bf16(const float* __restrict__ src, __nv_bfloat16* __restrict__ dst,
                             int rows, int nK32, int srcStride, int Nvalid, int Kvalid, int slot) {
    const float s = get_scale(slot);
    uint32_t* d32 = (uint32_t*)dst;
    const int nK16 = nK32 * 2;
    size_t total = (size_t)rows * nK32;
    for (size_t i = (size_t)blockIdx.x * blockDim.x + threadIdx.x; i < total;
         i += (size_t)gridDim.x * blockDim.x) {
        int n = (int)(i % rows);
        int k32 = (int)(i / rows);
        int kb0 = k32 * 32;
        float f[32];
        if (n < Nvalid) {
            size_t off = (size_t)n * srcStride + kb0;
            if (kb0 + 32 <= Kvalid) {
                load32(src + off, f, (off & 3) == 0);
            } else {
                #pragma unroll
                for (int j = 0; j < 32; j++)
                    f[j] = (kb0 + j < Kvalid) ? __ldg(src + off + j) : 0.0f;
            }
        } else {
            #pragma unroll
            for (int j = 0; j < 32; j++) f[j] = 0.0f;
        }
        int ntile = n >> 7, nr = n & 127;
        int n8 = nr >> 3, g = nr & 7;
        #pragma unroll
        for (int kh = 0; kh < 2; kh++) {
            int k16 = k32 * 2 + kh;
            uint32_t* base = d32 + (size_t)(ntile * nK16 + k16) * 1024 + n8 * 64 + 8 * g;
            const float* fk = f + kh * 16;
            uint32_t out[8];
            #pragma unroll
            for (int t = 0; t < 4; t++) {
                out[2 * t]     = bf2(fk[2 * t],     fk[2 * t + 1], s);
                out[2 * t + 1] = bf2(fk[8 + 2 * t], fk[9 + 2 * t], s);
            }
            *(uint4*)base       = *(const uint4*)&out[0];
            *(uint4*)(base + 4) = *(const uint4*)&out[4];
        }
    }
}

// ---- act = silu(q(gate)) * q(up) in place into gate; absmax -> slot 6 ----
__global__ void k_act(float* __restrict__ gate, const float* __restrict__ up, size_t n4) {
    float sg = get_scale(4), su = get_scale(5);
    float m = 0.0f;
    size_t i = (size_t)blockIdx.x * blockDim.x + threadIdx.x;
    size_t st = (size_t)gridDim.x * blockDim.x;
    float4* g4 = (float4*)gate;
    const float4* u4 = (const float4*)up;
    for (; i < n4; i += st) {
        float4 gv = g4[i];
        float4 uv = u4[i];
        float* gp = (float*)&gv;
        const float* uq4 = (const float*)&uv;
        #pragma unroll
        for (int k = 0; k < 4; k++) {
            float gq = quant_round(gp[k], sg) * sg;
            float uq = quant_round(uq4[k], su) * su;
            float a = gq * (1.0f / (1.0f + expf(-gq))) * uq;
            gp[k] = a;
            m = fmaxf(m, fabsf(a));
        }
        g4[i] = gv;
    }
    #pragma unroll
    for (int o = 16; o; o >>= 1) m = fmaxf(m, __shfl_xor_sync(0xffffffffu, m, o));
    if ((threadIdx.x & 31) == 0) atomicMaxPosF(&g_absmax[6], m);
}

// ---------------- bf16 HMMA GEMM ----------------
// One stage = 16KB = K32 (2 k16-chunks): A 8KB + B 8KB. Tile stride = KS*8192 bytes.
template<bool DO_AMAX>
__global__ void __launch_bounds__(256, 2)
k_gemm(const __nv_bfloat16* __restrict__ A, const __nv_bfloat16* __restrict__ B,
       const float* __restrict__ bias, float* __restrict__ C,
       int nK32, int Nvalid, int Cstride, int sa, int sb, int amax_slot) {
    extern __shared__ __align__(16) char smem[];   // NSTAGE * 16KB
    const int tid = threadIdx.x, lane = tid & 31, wid = tid >> 5;
    const int wm = wid >> 2, wn = wid & 3;         // warp grid 2 x 4 (64x32 warp tile)
    const int mtile = blockIdx.y, ntile = blockIdx.x;

    const int KS = nK32;                            // stages (K=32 each)
    const char* Ag = (const char*)A + (size_t)mtile * KS * 8192;
    const char* Bg = (const char*)B + (size_t)ntile * KS * 8192;

    float acc[4][4][4];
    #pragma unroll
    for (int i = 0; i < 4; i++)
        #pragma unroll
        for (int j = 0; j < 4; j++)
            #pragma unroll
            for (int r = 0; r < 4; r++) acc[i][j][r] = 0.0f;

    const uint32_t sbase = smem_u32(smem);
    const uint32_t co = (uint32_t)tid * 16u;

    auto issue = [&](int st) {
        uint32_t buf = sbase + (uint32_t)(st % NSTAGE) * 16384u;
        const char* ga = Ag + (size_t)st * 8192;
        const char* gb = Bg + (size_t)st * 8192;
        CP_ASYNC16(buf + co,          ga + co);
        CP_ASYNC16(buf + co + 4096,   ga + co + 4096);
        CP_ASYNC16(buf + co + 8192,   gb + co);
        CP_ASYNC16(buf + co + 12288,  gb + co + 4096);
    };

    #pragma unroll
    for (int p = 0; p < NSTAGE - 1; p++) {
        if (p < KS) issue(p);
        CP_COMMIT();
    }

    for (int c = 0; c < KS; c++) {
        CP_WAIT(NSTAGE - 2);
        __syncthreads();
        if (c + NSTAGE - 1 < KS) issue(c + NSTAGE - 1);
        CP_COMMIT();

        const char* bufA = smem + (c % NSTAGE) * 16384;
        const char* bufB = bufA + 8192;
        #pragma unroll
        for (int kk = 0; kk < 2; kk++) {      // two k16 chunks per stage
            int4 av[4];
            int2 bv[4];
            #pragma unroll
            for (int i = 0; i < 4; i++)
                av[i] = *(const int4*)(bufA + (((kk * 8 + wm * 4 + i) * 32 + lane) << 4));
            #pragma unroll
            for (int j = 0; j < 4; j++)
                bv[j] = *(const int2*)(bufB + (((kk * 16 + wn * 4 + j) * 32 + lane) << 3));
            #pragma unroll
            for (int i = 0; i < 4; i++)
                #pragma unroll
                for (int j = 0; j < 4; j++)
                    HMMA(acc[i][j], av[i], bv[j]);
        }
    }

    // epilogue: scale + bias (+ absmax)
    const float sab = get_scale(sa) * get_scale(sb);
    const int g = lane >> 2, t = lane & 3;
    float vmax = 0.0f;
    #pragma unroll
    for (int i = 0; i < 4; i++) {
        int row0 = mtile * 128 + wm * 64 + i * 16 + g;
        #pragma unroll
        for (int j = 0; j < 4; j++) {
            int col = ntile * 128 + wn * 32 + j * 8 + t * 2;
            if (col < Nvalid) {
                float b0 = __ldg(&bias[col]), b1 = __ldg(&bias[col + 1]);
                float2 v0, v1;
                v0.x = fmaf(acc[i][j][0], sab, b0);
                v0.y = fmaf(acc[i][j][1], sab, b1);
                v1.x = fmaf(acc[i][j][2], sab, b0);
                v1.y = fmaf(acc[i][j][3], sab, b1);
                *(float2*)(C + (size_t)row0 * Cstride + col) = v0;
                *(float2*)(C + (size_t)(row0 + 8) * Cstride + col) = v1;
                if (DO_AMAX)
                    vmax = fmaxf(vmax, fmaxf(fmaxf(fabsf(v0.x), fabsf(v0.y)),
                                             fmaxf(fabsf(v1.x), fabsf(v1.y))));
            }
        }
    }
    if (DO_AMAX) {
        #pragma unroll
        for (int o = 16; o; o >>= 1) vmax = fmaxf(vmax, __shfl_xor_sync(0xffffffffu, vmax, o));
        if (lane == 0) atomicMaxPosF(&g_absmax[amax_slot], vmax);
    }
}

// ---------------- launch ----------------
extern "C" void kernel_launch(void* const* d_in, const int* in_sizes, int n_in,
                              void* d_out, int out_size) {
    (void)in_sizes; (void)n_in; (void)out_size;
    const float* x  = (const float*)d_in[0];
    const float* wg = (const float*)d_in[1];
    const float* wu = (const float*)d_in[2];
    const float* wd = (const float*)d_in[3];
    const float* bg = (const float*)d_in[4];
    const float* bu = (const float*)d_in[5];
    const float* bd = (const float*)d_in[6];
    float* out = (float*)d_out;

    __nv_bfloat16 *pXbf, *pGbf, *pUbf, *pDbf, *pAbf;
    float *pGate, *pUp;
    cudaGetSymbolAddress((void**)&pXbf, g_Xbf);
    cudaGetSymbolAddress((void**)&pGbf, g_Gbf);
    cudaGetSymbolAddress((void**)&pUbf, g_Ubf);
    cudaGetSymbolAddress((void**)&pDbf, g_Dbf);
    cudaGetSymbolAddress((void**)&pAbf, g_Abf);
    cudaGetSymbolAddress((void**)&pGate, g_gate);
    cudaGetSymbolAddress((void**)&pUp, g_up);

    cudaFuncSetAttribute(k_gemm<true>,  cudaFuncAttributeMaxDynamicSharedMemorySize, NSTAGE * 16384);
    cudaFuncSetAttribute(k_gemm<false>, cudaFuncAttributeMaxDynamicSharedMemorySize, NSTAGE * 16384);

    const int RT = 256;
    const int nK32g = DMODEL / 32;   // 128
    const int nK32d = HPADK / 32;    // 342

    dim3 g1(HPADN / 128, TOKENS / 128);
    dim3 g2(DMODEL / 128, TOKENS / 128);

    // capture is launch index 5 (-s 5 -c 1) -> gate GEMM
    k_init<<<1, 8>>>();                                                        // 0
    k_absmax_all<<<2048, RT>>>(x, wg, wu, wd);                                 // 1
    k_packA_bf16<<<((size_t)TOKENS * nK32g + RT - 1) / RT, RT>>>(              // 2
        x, pXbf, TOKENS, nK32g, DMODEL, DMODEL, 0);
    k_packB_bf16<<<((size_t)HPADN * nK32g + RT - 1) / RT, RT>>>(               // 3
        wg, pGbf, HPADN, nK32g, DMODEL, HIDDEN, DMODEL, 1);
    k_packB_bf16<<<((size_t)HPADN * nK32g + RT - 1) / RT, RT>>>(               // 4
        wu, pUbf, HPADN, nK32g, DMODEL, HIDDEN, DMODEL, 2);
    k_gemm<true><<<g1, 256, NSTAGE * 16384>>>(                                 // 5  <- ncu capture
        pXbf, pGbf, bg, pGate, nK32g, HIDDEN, HPADK, 0, 1, 4);
    k_gemm<true><<<g1, 256, NSTAGE * 16384>>>(                                 // 6
        pXbf, pUbf, bu, pUp, nK32g, HIDDEN, HPADK, 0, 2, 5);
    k_packB_bf16<<<((size_t)DMODEL * nK32d + RT - 1) / RT, RT>>>(              // 7
        wd, pDbf, DMODEL, nK32d, HIDDEN, DMODEL, HIDDEN, 3);
    k_act<<<2048, RT>>>(pGate, pUp, (size_t)TOKENS * HPADK / 4);               // 8
    k_packA_bf16<<<((size_t)TOKENS * nK32d + RT - 1) / RT, RT>>>(              // 9
        pGate, pAbf, TOKENS, nK32d, HPADK, HPADK, 6);
    k_gemm<false><<<g2, 256, NSTAGE * 16384>>>(                                // 10
        pAbf, pDbf, bd, out, nK32d, DMODEL, DMODEL, 6, 3, -1);
}

// round 9
// speedup vs baseline: 2.8934x; 1.0026x over previous
#include <cuda_runtime.h>
#include <cuda_bf16.h>
#include <cstdint>
#include <math.h>

#define TOKENS 4096
#define DMODEL 4096
#define HIDDEN 10922
#define HPADN  11008   // hidden padded to 128 (B rows / output cols for gate & up)
#define HPADK  10944   // hidden padded to 64; also activation buffer stride (mult of 4)
#define NSTAGE 4

// ---------------- device scratch (all bf16 frag-packed for HMMA) ----------------
__device__ __align__(256) __nv_bfloat16 g_Xbf[(size_t)TOKENS * DMODEL];   // A frags
__device__ __align__(256) __nv_bfloat16 g_Gbf[(size_t)HPADN * DMODEL];    // B frags
__device__ __align__(256) __nv_bfloat16 g_Ubf[(size_t)HPADN * DMODEL];    // B frags
__device__ __align__(256) __nv_bfloat16 g_Dbf[(size_t)DMODEL * HPADK];    // B frags
__device__ __align__(256) __nv_bfloat16 g_Abf[(size_t)TOKENS * HPADK];    // A frags
__device__ __align__(16) float g_gate[(size_t)TOKENS * HPADK];   // padded stride
__device__ __align__(16) float g_up  [(size_t)TOKENS * HPADK];   // padded stride
__device__ float g_absmax[8];   // 0:x 1:wg 2:wu 3:wd 4:gate 5:up 6:act

// ---------------- helpers ----------------
__device__ __forceinline__ void atomicMaxPosF(float* a, float v) {
    atomicMax((unsigned int*)a, __float_as_uint(v));
}
__device__ __forceinline__ float quant_round(float x, float s) {
    float r = rintf(__fdiv_rn(x, s));
    return fminf(fmaxf(r, -127.0f), 127.0f);
}
__device__ __forceinline__ float get_scale(int slot) {
    return fmaxf(__fdiv_rn(g_absmax[slot], 127.0f), 1e-8f);
}
__device__ __forceinline__ uint32_t smem_u32(const void* p) {
    uint32_t a;
    asm("{ .reg .u64 t; cvta.to.shared.u64 t, %1; cvt.u32.u64 %0, t; }" : "=r"(a) : "l"(p));
    return a;
}
__device__ __forceinline__ uint32_t bf2(float a, float b, float s) {
    __nv_bfloat16 lo = __float2bfloat16_rn(quant_round(a, s));
    __nv_bfloat16 hi = __float2bfloat16_rn(quant_round(b, s));
    return (uint32_t)__bfloat16_as_ushort(lo) | ((uint32_t)__bfloat16_as_ushort(hi) << 16);
}
// load 32 consecutive floats; p at least 8B-aligned; a16: 16B-aligned
__device__ __forceinline__ void load32(const float* __restrict__ p, float* f, bool a16) {
    if (a16) {
        #pragma unroll
        for (int q = 0; q < 8; q++) *(float4*)&f[q * 4] = __ldg((const float4*)p + q);
    } else {
        #pragma unroll
        for (int q = 0; q < 16; q++) *(float2*)&f[q * 2] = __ldg((const float2*)p + q);
    }
}
#define CP_ASYNC16(dst, src) \
    asm volatile("cp.async.cg.shared.global [%0], [%1], 16;" :: "r"(dst), "l"(src))
#define CP_COMMIT() asm volatile("cp.async.commit_group;")
#define CP_WAIT(n)  asm volatile("cp.async.wait_group %0;" :: "n"(n))

#define HMMA(acc, a, b) \
    asm volatile("mma.sync.aligned.m16n8k16.row.col.f32.bf16.bf16.f32 " \
        "{%0,%1,%2,%3}, {%4,%5,%6,%7}, {%8,%9}, {%0,%1,%2,%3};" \
        : "+f"((acc)[0]), "+f"((acc)[1]), "+f"((acc)[2]), "+f"((acc)[3]) \
        : "r"((a).x), "r"((a).y), "r"((a).z), "r"((a).w), "r"((b).x), "r"((b).y))

__global__ void k_init() { if (threadIdx.x < 8) g_absmax[threadIdx.x] = 0.0f; }

// ---- one kernel: absmax of all 4 inputs ----
__device__ __forceinline__ void absmax_seg(const float* __restrict__ t, size_t n4, int slot) {
    float m = 0.0f;
    size_t i = (size_t)blockIdx.x * blockDim.x + threadIdx.x;
    size_t st = (size_t)gridDim.x * blockDim.x;
    const float4* t4 = (const float4*)t;
    for (; i < n4; i += st) {
        float4 v = t4[i];
        m = fmaxf(m, fmaxf(fmaxf(fabsf(v.x), fabsf(v.y)), fmaxf(fabsf(v.z), fabsf(v.w))));
    }
    #pragma unroll
    for (int o = 16; o; o >>= 1) m = fmaxf(m, __shfl_xor_sync(0xffffffffu, m, o));
    if ((threadIdx.x & 31) == 0) atomicMaxPosF(&g_absmax[slot], m);
}
__global__ void k_absmax_all(const float* __restrict__ x, const float* __restrict__ wg,
                             const float* __restrict__ wu, const float* __restrict__ wd) {
    absmax_seg(x,  (size_t)TOKENS * DMODEL / 4, 0);
    absmax_seg(wg, (size_t)HIDDEN * DMODEL / 4, 1);
    absmax_seg(wu, (size_t)HIDDEN * DMODEL / 4, 2);
    absmax_seg(wd, (size_t)DMODEL * HIDDEN / 4, 3);
}

// ======== bf16 HMMA pack bodies (m16n8k16) ========
// A frag layout: [mtile][k16][m16][lane]x16B (regs a0..a3)
__device__ __forceinline__ void packA_body(const float* __restrict__ src,
                                           uint32_t* __restrict__ d32, float s,
                                           int rows, int nK32, int srcStride, int Kvalid,
                                           size_t gid, size_t gstride) {
    const int nK16 = nK32 * 2;
    size_t total = (size_t)rows * nK32;
    for (size_t i = gid; i < total; i += gstride) {
        int row = (int)(i % rows);
        int k32 = (int)(i / rows);
        int kb0 = k32 * 32;
        float f[32];
        if (kb0 + 32 <= Kvalid) {
            load32(src + (size_t)row * srcStride + kb0, f, true);
        } else {
            #pragma unroll
            for (int j = 0; j < 32; j++)
                f[j] = (kb0 + j < Kvalid) ? __ldg(src + (size_t)row * srcStride + kb0 + j) : 0.0f;
        }
        int mtile = row >> 7, rr = row & 127;
        int m16 = rr >> 4, g = rr & 7, rb = (rr >> 3) & 1;
        #pragma unroll
        for (int kh = 0; kh < 2; kh++) {
            int k16 = k32 * 2 + kh;
            uint32_t* base = d32 + (size_t)(mtile * nK16 + k16) * 1024 + m16 * 128 + 16 * g;
            const float* fk = f + kh * 16;
            #pragma unroll
            for (int t = 0; t < 4; t++) {
                base[4 * t + rb]     = bf2(fk[2 * t],     fk[2 * t + 1], s);
                base[4 * t + rb + 2] = bf2(fk[8 + 2 * t], fk[9 + 2 * t], s);
            }
        }
    }
}

// B frag layout: [ntile][k16][n8][lane]x8B (regs b0,b1); 8 contiguous words per thread
__device__ __forceinline__ void packB_body(const float* __restrict__ src,
                                           uint32_t* __restrict__ d32, float s,
                                           int rows, int nK32, int srcStride,
                                           int Nvalid, int Kvalid,
                                           size_t gid, size_t gstride) {
    const int nK16 = nK32 * 2;
    size_t total = (size_t)rows * nK32;
    for (size_t i = gid; i < total; i += gstride) {
        int n = (int)(i % rows);
        int k32 = (int)(i / rows);
        int kb0 = k32 * 32;
        float f[32];
        if (n < Nvalid) {
            size_t off = (size_t)n * srcStride + kb0;
            if (kb0 + 32 <= Kvalid) {
                load32(src + off, f, (off & 3) == 0);
            } else {
                #pragma unroll
                for (int j = 0; j < 32; j++)
                    f[j] = (kb0 + j < Kvalid) ? __ldg(src + off + j) : 0.0f;
            }
        } else {
            #pragma unroll
            for (int j = 0; j < 32; j++) f[j] = 0.0f;
        }
        int ntile = n >> 7, nr = n & 127;
        int n8 = nr >> 3, g = nr & 7;
        #pragma unroll
        for (int kh = 0; kh < 2; kh++) {
            int k16 = k32 * 2 + kh;
            uint32_t* base = d32 + (size_t)(ntile * nK16 + k16) * 1024 + n8 * 64 + 8 * g;
            const float* fk = f + kh * 16;
            uint32_t out[8];
            #pragma unroll
            for (int t = 0; t < 4; t++) {
                out[2 * t]     = bf2(fk[2 * t],     fk[2 * t + 1], s);
                out[2 * t + 1] = bf2(fk[8 + 2 * t], fk[9 + 2 * t], s);
            }
            *(uint4*)base       = *(const uint4*)&out[0];
            *(uint4*)(base + 4) = *(const uint4*)&out[4];
        }
    }
}

__global__ void k_packA_bf16(const float* __restrict__ src, __nv_bfloat16* __restrict__ dst,
                             int rows, int nK32, int srcStride, int Kvalid, int slot) {
    packA_body(src, (uint32_t*)dst, get_scale(slot), rows, nK32, srcStride, Kvalid,
               (size_t)blockIdx.x * blockDim.x + threadIdx.x,
               (size_t)gridDim.x * blockDim.x);
}
__global__ void k_packB_bf16(const float* __restrict__ src, __nv_bfloat16* __restrict__ dst,
                             int rows, int nK32, int srcStride, int Nvalid, int Kvalid, int slot) {
    packB_body(src, (uint32_t*)dst, get_scale(slot), rows, nK32, srcStride, Nvalid, Kvalid,
               (size_t)blockIdx.x * blockDim.x + threadIdx.x,
               (size_t)gridDim.x * blockDim.x);
}

// merged: packA(x) + packB(wg) in one launch (so gate GEMM is launch index 3)
__global__ void k_pack_xg(const float* __restrict__ x, __nv_bfloat16* __restrict__ dx,
                          const float* __restrict__ wg, __nv_bfloat16* __restrict__ dg) {
    const size_t nA = (size_t)TOKENS * (DMODEL / 32);   // 16384 items
    size_t gid = (size_t)blockIdx.x * blockDim.x + threadIdx.x;
    size_t gstride = (size_t)gridDim.x * blockDim.x;
    packA_body(x, (uint32_t*)dx, get_scale(0), TOKENS, DMODEL / 32, DMODEL, DMODEL,
               gid, gstride);
    packB_body(wg, (uint32_t*)dg, get_scale(1), HPADN, DMODEL / 32, DMODEL, HIDDEN, DMODEL,
               gid, gstride);
    (void)nA;
}

// ---- act = silu(q(gate)) * q(up) in place into gate; absmax -> slot 6 ----
__global__ void k_act(float* __restrict__ gate, const float* __restrict__ up, size_t n4) {
    float sg = get_scale(4), su = get_scale(5);
    float m = 0.0f;
    size_t i = (size_t)blockIdx.x * blockDim.x + threadIdx.x;
    size_t st = (size_t)gridDim.x * blockDim.x;
    float4* g4 = (float4*)gate;
    const float4* u4 = (const float4*)up;
    for (; i < n4; i += st) {
        float4 gv = g4[i];
        float4 uv = u4[i];
        float* gp = (float*)&gv;
        const float* uq4 = (const float*)&uv;
        #pragma unroll
        for (int k = 0; k < 4; k++) {
            float gq = quant_round(gp[k], sg) * sg;
            float uq = quant_round(uq4[k], su) * su;
            float a = gq * (1.0f / (1.0f + expf(-gq))) * uq;
            gp[k] = a;
            m = fmaxf(m, fabsf(a));
        }
        g4[i] = gv;
    }
    #pragma unroll
    for (int o = 16; o; o >>= 1) m = fmaxf(m, __shfl_xor_sync(0xffffffffu, m, o));
    if ((threadIdx.x & 31) == 0) atomicMaxPosF(&g_absmax[6], m);
}

// ---------------- bf16 HMMA GEMM ----------------
// One stage = 16KB = K32 (2 k16-chunks): A 8KB + B 8KB. Tile stride = KS*8192 bytes.
template<bool DO_AMAX>
__global__ void __launch_bounds__(256, 2)
k_gemm(const __nv_bfloat16* __restrict__ A, const __nv_bfloat16* __restrict__ B,
       const float* __restrict__ bias, float* __restrict__ C,
       int nK32, int Nvalid, int Cstride, int sa, int sb, int amax_slot) {
    extern __shared__ __align__(16) char smem[];   // NSTAGE * 16KB
    const int tid = threadIdx.x, lane = tid & 31, wid = tid >> 5;
    const int wm = wid >> 2, wn = wid & 3;         // warp grid 2 x 4 (64x32 warp tile)
    const int mtile = blockIdx.y, ntile = blockIdx.x;

    const int KS = nK32;                            // stages (K=32 each)
    const char* Ag = (const char*)A + (size_t)mtile * KS * 8192;
    const char* Bg = (const char*)B + (size_t)ntile * KS * 8192;

    float acc[4][4][4];
    #pragma unroll
    for (int i = 0; i < 4; i++)
        #pragma unroll
        for (int j = 0; j < 4; j++)
            #pragma unroll
            for (int r = 0; r < 4; r++) acc[i][j][r] = 0.0f;

    const uint32_t sbase = smem_u32(smem);
    const uint32_t co = (uint32_t)tid * 16u;

    auto issue = [&](int st) {
        uint32_t buf = sbase + (uint32_t)(st % NSTAGE) * 16384u;
        const char* ga = Ag + (size_t)st * 8192;
        const char* gb = Bg + (size_t)st * 8192;
        CP_ASYNC16(buf + co,          ga + co);
        CP_ASYNC16(buf + co + 4096,   ga + co + 4096);
        CP_ASYNC16(buf + co + 8192,   gb + co);
        CP_ASYNC16(buf + co + 12288,  gb + co + 4096);
    };

    #pragma unroll
    for (int p = 0; p < NSTAGE - 1; p++) {
        if (p < KS) issue(p);
        CP_COMMIT();
    }

    for (int c = 0; c < KS; c++) {
        CP_WAIT(NSTAGE - 2);
        __syncthreads();
        if (c + NSTAGE - 1 < KS) issue(c + NSTAGE - 1);
        CP_COMMIT();

        const char* bufA = smem + (c % NSTAGE) * 16384;
        const char* bufB = bufA + 8192;
        #pragma unroll
        for (int kk = 0; kk < 2; kk++) {      // two k16 chunks per stage
            int4 av[4];
            int2 bv[4];
            #pragma unroll
            for (int i = 0; i < 4; i++)
                av[i] = *(const int4*)(bufA + (((kk * 8 + wm * 4 + i) * 32 + lane) << 4));
            #pragma unroll
            for (int j = 0; j < 4; j++)
                bv[j] = *(const int2*)(bufB + (((kk * 16 + wn * 4 + j) * 32 + lane) << 3));
            #pragma unroll
            for (int i = 0; i < 4; i++)
                #pragma unroll
                for (int j = 0; j < 4; j++)
                    HMMA(acc[i][j], av[i], bv[j]);
        }
    }

    // epilogue: scale + bias (+ absmax)
    const float sab = get_scale(sa) * get_scale(sb);
    const int g = lane >> 2, t = lane & 3;
    float vmax = 0.0f;
    #pragma unroll
    for (int i = 0; i < 4; i++) {
        int row0 = mtile * 128 + wm * 64 + i * 16 + g;
        #pragma unroll
        for (int j = 0; j < 4; j++) {
            int col = ntile * 128 + wn * 32 + j * 8 + t * 2;
            if (col < Nvalid) {
                float b0 = __ldg(&bias[col]), b1 = __ldg(&bias[col + 1]);
                float2 v0, v1;
                v0.x = fmaf(acc[i][j][0], sab, b0);
                v0.y = fmaf(acc[i][j][1], sab, b1);
                v1.x = fmaf(acc[i][j][2], sab, b0);
                v1.y = fmaf(acc[i][j][3], sab, b1);
                *(float2*)(C + (size_t)row0 * Cstride + col) = v0;
                *(float2*)(C + (size_t)(row0 + 8) * Cstride + col) = v1;
                if (DO_AMAX)
                    vmax = fmaxf(vmax, fmaxf(fmaxf(fabsf(v0.x), fabsf(v0.y)),
                                             fmaxf(fabsf(v1.x), fabsf(v1.y))));
            }
        }
    }
    if (DO_AMAX) {
        #pragma unroll
        for (int o = 16; o; o >>= 1) vmax = fmaxf(vmax, __shfl_xor_sync(0xffffffffu, vmax, o));
        if (lane == 0) atomicMaxPosF(&g_absmax[amax_slot], vmax);
    }
}

// ---------------- launch ----------------
extern "C" void kernel_launch(void* const* d_in, const int* in_sizes, int n_in,
                              void* d_out, int out_size) {
    (void)in_sizes; (void)n_in; (void)out_size;
    const float* x  = (const float*)d_in[0];
    const float* wg = (const float*)d_in[1];
    const float* wu = (const float*)d_in[2];
    const float* wd = (const float*)d_in[3];
    const float* bg = (const float*)d_in[4];
    const float* bu = (const float*)d_in[5];
    const float* bd = (const float*)d_in[6];
    float* out = (float*)d_out;

    __nv_bfloat16 *pXbf, *pGbf, *pUbf, *pDbf, *pAbf;
    float *pGate, *pUp;
    cudaGetSymbolAddress((void**)&pXbf, g_Xbf);
    cudaGetSymbolAddress((void**)&pGbf, g_Gbf);
    cudaGetSymbolAddress((void**)&pUbf, g_Ubf);
    cudaGetSymbolAddress((void**)&pDbf, g_Dbf);
    cudaGetSymbolAddress((void**)&pAbf, g_Abf);
    cudaGetSymbolAddress((void**)&pGate, g_gate);
    cudaGetSymbolAddress((void**)&pUp, g_up);

    cudaFuncSetAttribute(k_gemm<true>,  cudaFuncAttributeMaxDynamicSharedMemorySize, NSTAGE * 16384);
    cudaFuncSetAttribute(k_gemm<false>, cudaFuncAttributeMaxDynamicSharedMemorySize, NSTAGE * 16384);

    const int RT = 256;
    const int nK32g = DMODEL / 32;   // 128
    const int nK32d = HPADK / 32;    // 342

    dim3 g1(HPADN / 128, TOKENS / 128);
    dim3 g2(DMODEL / 128, TOKENS / 128);

    // ncu captures launch index 3 -> gate GEMM there
    k_init<<<1, 8>>>();                                                        // 0
    k_absmax_all<<<2048, RT>>>(x, wg, wu, wd);                                 // 1
    k_pack_xg<<<4096, RT>>>(x, pXbf, wg, pGbf);                                // 2
    k_gemm<true><<<g1, 256, NSTAGE * 16384>>>(                                 // 3  <- ncu capture
        pXbf, pGbf, bg, pGate, nK32g, HIDDEN, HPADK, 0, 1, 4);
    k_packB_bf16<<<((size_t)HPADN * nK32g + RT - 1) / RT, RT>>>(               // 4
        wu, pUbf, HPADN, nK32g, DMODEL, HIDDEN, DMODEL, 2);
    k_gemm<true><<<g1, 256, NSTAGE * 16384>>>(                                 // 5
        pXbf, pUbf, bu, pUp, nK32g, HIDDEN, HPADK, 0, 2, 5);
    k_packB_bf16<<<((size_t)DMODEL * nK32d + RT - 1) / RT, RT>>>(              // 6
        wd, pDbf, DMODEL, nK32d, HIDDEN, DMODEL, HIDDEN, 3);
    k_act<<<2048, RT>>>(pGate, pUp, (size_t)TOKENS * HPADK / 4);               // 7
    k_packA_bf16<<<((size_t)TOKENS * nK32d + RT - 1) / RT, RT>>>(              // 8
        pGate, pAbf, TOKENS, nK32d, HPADK, HPADK, 6);
    k_gemm<false><<<g2, 256, NSTAGE * 16384>>>(                                // 9
        pAbf, pDbf, bd, out, nK32d, DMODEL, DMODEL, 6, 3, -1);
}

// round 10
// speedup vs baseline: 3.0516x; 1.0547x over previous
#include <cuda_runtime.h>
#include <cuda_bf16.h>
#include <cstdint>
#include <math.h>

#define TOKENS 4096
#define DMODEL 4096
#define HIDDEN 10922
#define HPADN  11008   // hidden padded to 128 (B rows / output cols for gate & up)
#define HPADK  10944   // hidden padded to 64; also activation buffer stride (mult of 4)
#define NSTAGE 3       // pipeline stages, each K=64 (A 16KB + B 16KB = 32KB)
#define STAGE_BYTES 32768

// ---------------- device scratch (all bf16 frag-packed for HMMA) ----------------
__device__ __align__(256) __nv_bfloat16 g_Xbf[(size_t)TOKENS * DMODEL];   // A frags
__device__ __align__(256) __nv_bfloat16 g_Gbf[(size_t)HPADN * DMODEL];    // B frags
__device__ __align__(256) __nv_bfloat16 g_Ubf[(size_t)HPADN * DMODEL];    // B frags
__device__ __align__(256) __nv_bfloat16 g_Dbf[(size_t)DMODEL * HPADK];    // B frags
__device__ __align__(256) __nv_bfloat16 g_Abf[(size_t)TOKENS * HPADK];    // A frags
__device__ __align__(16) float g_gate[(size_t)TOKENS * HPADK];   // padded stride
__device__ __align__(16) float g_up  [(size_t)TOKENS * HPADK];   // padded stride
__device__ float g_absmax[8];   // 0:x 1:wg 2:wu 3:wd 4:gate 5:up 6:act

// ---------------- helpers ----------------
__device__ __forceinline__ void atomicMaxPosF(float* a, float v) {
    atomicMax((unsigned int*)a, __float_as_uint(v));
}
__device__ __forceinline__ float quant_round(float x, float s) {
    float r = rintf(__fdiv_rn(x, s));
    return fminf(fmaxf(r, -127.0f), 127.0f);
}
__device__ __forceinline__ float get_scale(int slot) {
    return fmaxf(__fdiv_rn(g_absmax[slot], 127.0f), 1e-8f);
}
__device__ __forceinline__ uint32_t smem_u32(const void* p) {
    uint32_t a;
    asm("{ .reg .u64 t; cvta.to.shared.u64 t, %1; cvt.u32.u64 %0, t; }" : "=r"(a) : "l"(p));
    return a;
}
__device__ __forceinline__ uint32_t bf2(float a, float b, float s) {
    __nv_bfloat16 lo = __float2bfloat16_rn(quant_round(a, s));
    __nv_bfloat16 hi = __float2bfloat16_rn(quant_round(b, s));
    return (uint32_t)__bfloat16_as_ushort(lo) | ((uint32_t)__bfloat16_as_ushort(hi) << 16);
}
// load 32 consecutive floats; p at least 8B-aligned; a16: 16B-aligned
__device__ __forceinline__ void load32(const float* __restrict__ p, float* f, bool a16) {
    if (a16) {
        #pragma unroll
        for (int q = 0; q < 8; q++) *(float4*)&f[q * 4] = __ldg((const float4*)p + q);
    } else {
        #pragma unroll
        for (int q = 0; q < 16; q++) *(float2*)&f[q * 2] = __ldg((const float2*)p + q);
    }
}
#define CP_ASYNC16(dst, src) \
    asm volatile("cp.async.cg.shared.global [%0], [%1], 16;" :: "r"(dst), "l"(src))
#define CP_COMMIT() asm volatile("cp.async.commit_group;")
#define CP_WAIT(n)  asm volatile("cp.async.wait_group %0;" :: "n"(n))

#define HMMA(acc, a, b) \
    asm volatile("mma.sync.aligned.m16n8k16.row.col.f32.bf16.bf16.f32 " \
        "{%0,%1,%2,%3}, {%4,%5,%6,%7}, {%8,%9}, {%0,%1,%2,%3};" \
        : "+f"((acc)[0]), "+f"((acc)[1]), "+f"((acc)[2]), "+f"((acc)[3]) \
        : "r"((a).x), "r"((a).y), "r"((a).z), "r"((a).w), "r"((b).x), "r"((b).y))

__global__ void k_init() { if (threadIdx.x < 8) g_absmax[threadIdx.x] = 0.0f; }

// ---- one kernel: absmax of all 4 inputs ----
__device__ __forceinline__ void absmax_seg(const float* __restrict__ t, size_t n4, int slot) {
    float m = 0.0f;
    size_t i = (size_t)blockIdx.x * blockDim.x + threadIdx.x;
    size_t st = (size_t)gridDim.x * blockDim.x;
    const float4* t4 = (const float4*)t;
    for (; i < n4; i += st) {
        float4 v = t4[i];
        m = fmaxf(m, fmaxf(fmaxf(fabsf(v.x), fabsf(v.y)), fmaxf(fabsf(v.z), fabsf(v.w))));
    }
    #pragma unroll
    for (int o = 16; o; o >>= 1) m = fmaxf(m, __shfl_xor_sync(0xffffffffu, m, o));
    if ((threadIdx.x & 31) == 0) atomicMaxPosF(&g_absmax[slot], m);
}
__global__ void k_absmax_all(const float* __restrict__ x, const float* __restrict__ wg,
                             const float* __restrict__ wu, const float* __restrict__ wd) {
    absmax_seg(x,  (size_t)TOKENS * DMODEL / 4, 0);
    absmax_seg(wg, (size_t)HIDDEN * DMODEL / 4, 1);
    absmax_seg(wu, (size_t)HIDDEN * DMODEL / 4, 2);
    absmax_seg(wd, (size_t)DMODEL * HIDDEN / 4, 3);
}

// ======== bf16 HMMA pack bodies (m16n8k16) ========
// A frag layout: [mtile][k16][m16][lane]x16B (regs a0..a3)
__device__ __forceinline__ void packA_body(const float* __restrict__ src,
                                           uint32_t* __restrict__ d32, float s,
                                           int rows, int nK32, int srcStride, int Kvalid,
                                           size_t gid, size_t gstride) {
    const int nK16 = nK32 * 2;
    size_t total = (size_t)rows * nK32;
    for (size_t i = gid; i < total; i += gstride) {
        int row = (int)(i % rows);
        int k32 = (int)(i / rows);
        int kb0 = k32 * 32;
        float f[32];
        if (kb0 + 32 <= Kvalid) {
            load32(src + (size_t)row * srcStride + kb0, f, true);
        } else {
            #pragma unroll
            for (int j = 0; j < 32; j++)
                f[j] = (kb0 + j < Kvalid) ? __ldg(src + (size_t)row * srcStride + kb0 + j) : 0.0f;
        }
        int mtile = row >> 7, rr = row & 127;
        int m16 = rr >> 4, g = rr & 7, rb = (rr >> 3) & 1;
        #pragma unroll
        for (int kh = 0; kh < 2; kh++) {
            int k16 = k32 * 2 + kh;
            uint32_t* base = d32 + (size_t)(mtile * nK16 + k16) * 1024 + m16 * 128 + 16 * g;
            const float* fk = f + kh * 16;
            #pragma unroll
            for (int t = 0; t < 4; t++) {
                base[4 * t + rb]     = bf2(fk[2 * t],     fk[2 * t + 1], s);
                base[4 * t + rb + 2] = bf2(fk[8 + 2 * t], fk[9 + 2 * t], s);
            }
        }
    }
}

// B frag layout: [ntile][k16][n8][lane]x8B (regs b0,b1); 8 contiguous words per thread
__device__ __forceinline__ void packB_body(const float* __restrict__ src,
                                           uint32_t* __restrict__ d32, float s,
                                           int rows, int nK32, int srcStride,
                                           int Nvalid, int Kvalid,
                                           size_t gid, size_t gstride) {
    const int nK16 = nK32 * 2;
    size_t total = (size_t)rows * nK32;
    for (size_t i = gid; i < total; i += gstride) {
        int n = (int)(i % rows);
        int k32 = (int)(i / rows);
        int kb0 = k32 * 32;
        float f[32];
        if (n < Nvalid) {
            size_t off = (size_t)n * srcStride + kb0;
            if (kb0 + 32 <= Kvalid) {
                load32(src + off, f, (off & 3) == 0);
            } else {
                #pragma unroll
                for (int j = 0; j < 32; j++)
                    f[j] = (kb0 + j < Kvalid) ? __ldg(src + off + j) : 0.0f;
            }
        } else {
            #pragma unroll
            for (int j = 0; j < 32; j++) f[j] = 0.0f;
        }
        int ntile = n >> 7, nr = n & 127;
        int n8 = nr >> 3, g = nr & 7;
        #pragma unroll
        for (int kh = 0; kh < 2; kh++) {
            int k16 = k32 * 2 + kh;
            uint32_t* base = d32 + (size_t)(ntile * nK16 + k16) * 1024 + n8 * 64 + 8 * g;
            const float* fk = f + kh * 16;
            uint32_t out[8];
            #pragma unroll
            for (int t = 0; t < 4; t++) {
                out[2 * t]     = bf2(fk[2 * t],     fk[2 * t + 1], s);
                out[2 * t + 1] = bf2(fk[8 + 2 * t], fk[9 + 2 * t], s);
            }
            *(uint4*)base       = *(const uint4*)&out[0];
            *(uint4*)(base + 4) = *(const uint4*)&out[4];
        }
    }
}

__global__ void k_packA_bf16(const float* __restrict__ src, __nv_bfloat16* __restrict__ dst,
                             int rows, int nK32, int srcStride, int Kvalid, int slot) {
    packA_body(src, (uint32_t*)dst, get_scale(slot), rows, nK32, srcStride, Kvalid,
               (size_t)blockIdx.x * blockDim.x + threadIdx.x,
               (size_t)gridDim.x * blockDim.x);
}
__global__ void k_packB_bf16(const float* __restrict__ src, __nv_bfloat16* __restrict__ dst,
                             int rows, int nK32, int srcStride, int Nvalid, int Kvalid, int slot) {
    packB_body(src, (uint32_t*)dst, get_scale(slot), rows, nK32, srcStride, Nvalid, Kvalid,
               (size_t)blockIdx.x * blockDim.x + threadIdx.x,
               (size_t)gridDim.x * blockDim.x);
}

// merged: packA(x) + packB(wg) in one launch (so gate GEMM is launch index 3)
__global__ void k_pack_xg(const float* __restrict__ x, __nv_bfloat16* __restrict__ dx,
                          const float* __restrict__ wg, __nv_bfloat16* __restrict__ dg) {
    size_t gid = (size_t)blockIdx.x * blockDim.x + threadIdx.x;
    size_t gstride = (size_t)gridDim.x * blockDim.x;
    packA_body(x, (uint32_t*)dx, get_scale(0), TOKENS, DMODEL / 32, DMODEL, DMODEL,
               gid, gstride);
    packB_body(wg, (uint32_t*)dg, get_scale(1), HPADN, DMODEL / 32, DMODEL, HIDDEN, DMODEL,
               gid, gstride);
}

// ---- act = silu(q(gate)) * q(up) in place into gate; absmax -> slot 6 ----
__global__ void k_act(float* __restrict__ gate, const float* __restrict__ up, size_t n4) {
    float sg = get_scale(4), su = get_scale(5);
    float m = 0.0f;
    size_t i = (size_t)blockIdx.x * blockDim.x + threadIdx.x;
    size_t st = (size_t)gridDim.x * blockDim.x;
    float4* g4 = (float4*)gate;
    const float4* u4 = (const float4*)up;
    for (; i < n4; i += st) {
        float4 gv = g4[i];
        float4 uv = u4[i];
        float* gp = (float*)&gv;
        const float* uq4 = (const float*)&uv;
        #pragma unroll
        for (int k = 0; k < 4; k++) {
            float gq = quant_round(gp[k], sg) * sg;
            float uq = quant_round(uq4[k], su) * su;
            float a = gq * (1.0f / (1.0f + expf(-gq))) * uq;
            gp[k] = a;
            m = fmaxf(m, fabsf(a));
        }
        g4[i] = gv;
    }
    #pragma unroll
    for (int o = 16; o; o >>= 1) m = fmaxf(m, __shfl_xor_sync(0xffffffffu, m, o));
    if ((threadIdx.x & 31) == 0) atomicMaxPosF(&g_absmax[6], m);
}

// ---------------- bf16 HMMA GEMM ----------------
// One stage = 32KB = K64 (4 k16-chunks): A 16KB + B 16KB. Tile stride = KS*16384 bytes per operand.
template<bool DO_AMAX>
__global__ void __launch_bounds__(256, 2)
k_gemm(const __nv_bfloat16* __restrict__ A, const __nv_bfloat16* __restrict__ B,
       const float* __restrict__ bias, float* __restrict__ C,
       int nK32, int Nvalid, int Cstride, int sa, int sb, int amax_slot) {
    extern __shared__ __align__(16) char smem[];   // NSTAGE * 32KB
    const int tid = threadIdx.x, lane = tid & 31, wid = tid >> 5;
    const int wm = wid >> 2, wn = wid & 3;         // warp grid 2 x 4 (64x32 warp tile)
    const int mtile = blockIdx.y, ntile = blockIdx.x;

    const int KS = nK32 >> 1;                       // stages (K=64 each); nK32 always even
    const char* Ag = (const char*)A + (size_t)mtile * KS * 16384;
    const char* Bg = (const char*)B + (size_t)ntile * KS * 16384;

    float acc[4][4][4];
    #pragma unroll
    for (int i = 0; i < 4; i++)
        #pragma unroll
        for (int j = 0; j < 4; j++)
            #pragma unroll
            for (int r = 0; r < 4; r++) acc[i][j][r] = 0.0f;

    const uint32_t sbase = smem_u32(smem);
    const uint32_t co = (uint32_t)tid * 16u;

    auto issue = [&](int st) {
        uint32_t buf = sbase + (uint32_t)(st % NSTAGE) * (uint32_t)STAGE_BYTES;
        const char* ga = Ag + (size_t)st * 16384;
        const char* gb = Bg + (size_t)st * 16384;
        #pragma unroll
        for (int w = 0; w < 4; w++) {
            CP_ASYNC16(buf + co + w * 4096u,          ga + co + w * 4096u);
            CP_ASYNC16(buf + co + w * 4096u + 16384u, gb + co + w * 4096u);
        }
    };

    #pragma unroll
    for (int p = 0; p < NSTAGE - 1; p++) {
        if (p < KS) issue(p);
        CP_COMMIT();
    }

    for (int c = 0; c < KS; c++) {
        CP_WAIT(NSTAGE - 2);
        __syncthreads();
        if (c + NSTAGE - 1 < KS) issue(c + NSTAGE - 1);
        CP_COMMIT();

        const char* bufA = smem + (c % NSTAGE) * STAGE_BYTES;
        const char* bufB = bufA + 16384;
        #pragma unroll
        for (int kk = 0; kk < 4; kk++) {      // four k16 chunks per stage
            int4 av[4];
            int2 bv[4];
            #pragma unroll
            for (int i = 0; i < 4; i++)
                av[i] = *(const int4*)(bufA + (((kk * 8 + wm * 4 + i) * 32 + lane) << 4));
            #pragma unroll
            for (int j = 0; j < 4; j++)
                bv[j] = *(const int2*)(bufB + (((kk * 16 + wn * 4 + j) * 32 + lane) << 3));
            #pragma unroll
            for (int i = 0; i < 4; i++)
                #pragma unroll
                for (int j = 0; j < 4; j++)
                    HMMA(acc[i][j], av[i], bv[j]);
        }
    }

    // epilogue: scale + bias (+ absmax)
    const float sab = get_scale(sa) * get_scale(sb);
    const int g = lane >> 2, t = lane & 3;
    float vmax = 0.0f;
    #pragma unroll
    for (int i = 0; i < 4; i++) {
        int row0 = mtile * 128 + wm * 64 + i * 16 + g;
        #pragma unroll
        for (int j = 0; j < 4; j++) {
            int col = ntile * 128 + wn * 32 + j * 8 + t * 2;
            if (col < Nvalid) {
                float b0 = __ldg(&bias[col]), b1 = __ldg(&bias[col + 1]);
                float2 v0, v1;
                v0.x = fmaf(acc[i][j][0], sab, b0);
                v0.y = fmaf(acc[i][j][1], sab, b1);
                v1.x = fmaf(acc[i][j][2], sab, b0);
                v1.y = fmaf(acc[i][j][3], sab, b1);
                *(float2*)(C + (size_t)row0 * Cstride + col) = v0;
                *(float2*)(C + (size_t)(row0 + 8) * Cstride + col) = v1;
                if (DO_AMAX)
                    vmax = fmaxf(vmax, fmaxf(fmaxf(fabsf(v0.x), fabsf(v0.y)),
                                             fmaxf(fabsf(v1.x), fabsf(v1.y))));
            }
        }
    }
    if (DO_AMAX) {
        #pragma unroll
        for (int o = 16; o; o >>= 1) vmax = fmaxf(vmax, __shfl_xor_sync(0xffffffffu, vmax, o));
        if (lane == 0) atomicMaxPosF(&g_absmax[amax_slot], vmax);
    }
}

// ---------------- launch ----------------
extern "C" void kernel_launch(void* const* d_in, const int* in_sizes, int n_in,
                              void* d_out, int out_size) {
    (void)in_sizes; (void)n_in; (void)out_size;
    const float* x  = (const float*)d_in[0];
    const float* wg = (const float*)d_in[1];
    const float* wu = (const float*)d_in[2];
    const float* wd = (const float*)d_in[3];
    const float* bg = (const float*)d_in[4];
    const float* bu = (const float*)d_in[5];
    const float* bd = (const float*)d_in[6];
    float* out = (float*)d_out;

    __nv_bfloat16 *pXbf, *pGbf, *pUbf, *pDbf, *pAbf;
    float *pGate, *pUp;
    cudaGetSymbolAddress((void**)&pXbf, g_Xbf);
    cudaGetSymbolAddress((void**)&pGbf, g_Gbf);
    cudaGetSymbolAddress((void**)&pUbf, g_Ubf);
    cudaGetSymbolAddress((void**)&pDbf, g_Dbf);
    cudaGetSymbolAddress((void**)&pAbf, g_Abf);
    cudaGetSymbolAddress((void**)&pGate, g_gate);
    cudaGetSymbolAddress((void**)&pUp, g_up);

    cudaFuncSetAttribute(k_gemm<true>,  cudaFuncAttributeMaxDynamicSharedMemorySize, NSTAGE * STAGE_BYTES);
    cudaFuncSetAttribute(k_gemm<false>, cudaFuncAttributeMaxDynamicSharedMemorySize, NSTAGE * STAGE_BYTES);

    const int RT = 256;
    const int nK32g = DMODEL / 32;   // 128
    const int nK32d = HPADK / 32;    // 342

    dim3 g1(HPADN / 128, TOKENS / 128);
    dim3 g2(DMODEL / 128, TOKENS / 128);

    // ncu captures launch index 3 -> gate GEMM there
    k_init<<<1, 8>>>();                                                        // 0
    k_absmax_all<<<2048, RT>>>(x, wg, wu, wd);                                 // 1
    k_pack_xg<<<4096, RT>>>(x, pXbf, wg, pGbf);                                // 2
    k_gemm<true><<<g1, 256, NSTAGE * STAGE_BYTES>>>(                           // 3  <- ncu capture
        pXbf, pGbf, bg, pGate, nK32g, HIDDEN, HPADK, 0, 1, 4);
    k_packB_bf16<<<((size_t)HPADN * nK32g + RT - 1) / RT, RT>>>(               // 4
        wu, pUbf, HPADN, nK32g, DMODEL, HIDDEN, DMODEL, 2);
    k_gemm<true><<<g1, 256, NSTAGE * STAGE_BYTES>>>(                           // 5
        pXbf, pUbf, bu, pUp, nK32g, HIDDEN, HPADK, 0, 2, 5);
    k_packB_bf16<<<((size_t)DMODEL * nK32d + RT - 1) / RT, RT>>>(              // 6
        wd, pDbf, DMODEL, nK32d, HIDDEN, DMODEL, HIDDEN, 3);
    k_act<<<2048, RT>>>(pGate, pUp, (size_t)TOKENS * HPADK / 4);               // 7
    k_packA_bf16<<<((size_t)TOKENS * nK32d + RT - 1) / RT, RT>>>(              // 8
        pGate, pAbf, TOKENS, nK32d, HPADK, HPADK, 6);
    k_gemm<false><<<g2, 256, NSTAGE * STAGE_BYTES>>>(                          // 9
        pAbf, pDbf, bd, out, nK32d, DMODEL, DMODEL, 6, 3, -1);
}